// round 2
// baseline (speedup 1.0000x reference)
#include <cuda_runtime.h>
#include <math.h>

#define BATCH 8192
#define HDIM  1024
#define GH    512
#define EMH   256
#define OUTD  18
#define GOUT  10

typedef unsigned long long u64;

// -------- scratch (device globals: allocation-free) --------
__device__ float g_h0  [BATCH*HDIM];
__device__ float g_base[BATCH*HDIM];
__device__ float g_eh  [BATCH*EMH];
__device__ float g_gin [BATCH*HDIM];
__device__ float g_gh  [BATCH*GH];
__device__ float g_logits[BATCH*GOUT];
__device__ float g_gates [BATCH*GOUT];
__device__ float g_out0[BATCH*HDIM];
__device__ float g_out1[BATCH*HDIM];
__device__ float g_out2[BATCH*HDIM];
__device__ float g_out3[BATCH*HDIM];
__device__ float g_inp [BATCH*HDIM];
__device__ float g_last[BATCH*HDIM];

// packed fp32x2 fma: d = a*b + d (lanewise, exact fp32)
__device__ __forceinline__ void ffma2(u64 &d, u64 a, u64 b) {
    asm("fma.rn.f32x2 %0, %1, %2, %0;" : "+l"(d) : "l"(a), "l"(b));
}
__device__ __forceinline__ u64 d2u(double d) { return __double_as_longlong(d); }
__device__ __forceinline__ float u_lo(u64 v) { return __int_as_float((int)(unsigned)v); }
__device__ __forceinline__ float u_hi(u64 v) { return __int_as_float((int)(unsigned)(v >> 32)); }
__device__ __forceinline__ void relu4(float4 &v) {
    v.x = fmaxf(v.x, 0.f); v.y = fmaxf(v.y, 0.f);
    v.z = fmaxf(v.z, 0.f); v.w = fmaxf(v.w, 0.f);
}

// =====================================================================
// Packed-FFMA2 tiled SGEMM: C = epi( op(A) @ B + bias )
// BM=BN=128, BK=8, 8x8 per thread (as 8x4 f32x2 pairs), 256 threads.
// A tile stored lane-duplicated in shared so f32x2 A operands are
// direct LDS; B pairs are naturally contiguous.
// Requires M%128==0, N%128==0, K%8==0 (true for all shapes here).
// =====================================================================
template<bool RELU_A, bool RELU_C, bool MUL_C>
__global__ __launch_bounds__(256)
void sgemm2_kernel(const float* __restrict__ A, const float* __restrict__ Bm,
                   const float* __restrict__ bias, const float* __restrict__ Cmul,
                   float* __restrict__ C, int M, int N, int K)
{
    __shared__ float Asd[8][256];   // duplicated: Asd[k][2m]=Asd[k][2m+1]=A[m,k]
    __shared__ float Bs [8][128];
    const int tid = threadIdx.x;
    const int bm = blockIdx.y * 128;
    const int bn = blockIdx.x * 128;

    const int arow = tid >> 1;          // 0..127
    const int acol = (tid & 1) << 2;    // 0 or 4
    const int brow = tid >> 5;          // 0..7
    const int bcol = (tid & 31) << 2;   // 0..124
    const int tx = (tid & 15) << 3;     // col offset within tile (8 cols = 4 pairs)
    const int ty = (tid >> 4) << 3;     // row offset within tile

    u64 acc[8][4];
#pragma unroll
    for (int i = 0; i < 8; i++)
#pragma unroll
        for (int j = 0; j < 4; j++) acc[i][j] = 0ull;

    const float* Ap = A + (bm + arow) * K + acol;
    const float* Bp = Bm + brow * N + bn + bcol;

    // prefetch first slab into registers
    float4 av = *(const float4*)Ap;
    if (RELU_A) relu4(av);
    float4 bv = *(const float4*)Bp;

    for (int k0 = 0; k0 < K; k0 += 8) {
        // stage current slab to shared (A duplicated via float2 stores)
        *(float2*)&Asd[acol + 0][2 * arow] = make_float2(av.x, av.x);
        *(float2*)&Asd[acol + 1][2 * arow] = make_float2(av.y, av.y);
        *(float2*)&Asd[acol + 2][2 * arow] = make_float2(av.z, av.z);
        *(float2*)&Asd[acol + 3][2 * arow] = make_float2(av.w, av.w);
        *(float4*)&Bs[brow][bcol] = bv;
        __syncthreads();

        // prefetch next slab (latency overlaps compute below)
        if (k0 + 8 < K) {
            av = *(const float4*)(Ap + k0 + 8);
            if (RELU_A) relu4(av);
            bv = *(const float4*)(Bp + (k0 + 8) * N);
        }

#pragma unroll
        for (int k = 0; k < 8; k++) {
            const double2 a0 = *(const double2*)&Asd[k][2 * ty];
            const double2 a1 = *(const double2*)&Asd[k][2 * ty + 4];
            const double2 a2 = *(const double2*)&Asd[k][2 * ty + 8];
            const double2 a3 = *(const double2*)&Asd[k][2 * ty + 12];
            const double2 b0 = *(const double2*)&Bs[k][tx];
            const double2 b1 = *(const double2*)&Bs[k][tx + 4];
            u64 ap[8], bp[4];
            ap[0] = d2u(a0.x); ap[1] = d2u(a0.y);
            ap[2] = d2u(a1.x); ap[3] = d2u(a1.y);
            ap[4] = d2u(a2.x); ap[5] = d2u(a2.y);
            ap[6] = d2u(a3.x); ap[7] = d2u(a3.y);
            bp[0] = d2u(b0.x); bp[1] = d2u(b0.y);
            bp[2] = d2u(b1.x); bp[3] = d2u(b1.y);
#pragma unroll
            for (int i = 0; i < 8; i++)
#pragma unroll
                for (int j = 0; j < 4; j++)
                    ffma2(acc[i][j], ap[i], bp[j]);
        }
        __syncthreads();
    }

#pragma unroll
    for (int i = 0; i < 8; i++) {
        const int row = bm + ty + i;
        float c[8];
#pragma unroll
        for (int j = 0; j < 4; j++) {
            c[2 * j + 0] = u_lo(acc[i][j]);
            c[2 * j + 1] = u_hi(acc[i][j]);
        }
#pragma unroll
        for (int j = 0; j < 8; j += 4) {
            const int col = bn + tx + j;
            float4 cv;
            cv.x = c[j + 0] + bias[col + 0];
            cv.y = c[j + 1] + bias[col + 1];
            cv.z = c[j + 2] + bias[col + 2];
            cv.w = c[j + 3] + bias[col + 3];
            if (RELU_C) relu4(cv);
            if (MUL_C) {
                const float4 mv = *(const float4*)(Cmul + row * N + col);
                cv.x *= mv.x; cv.y *= mv.y; cv.z *= mv.z; cv.w *= mv.w;
            }
            *(float4*)(C + row * N + col) = cv;
        }
    }
}

// em hidden: eh[b,j] = relu(em[b]*em_W0[j] + em_b0[j])
__global__ void ehidden_kernel(const float* __restrict__ em, const float* __restrict__ W0,
                               const float* __restrict__ b0, float* __restrict__ eh)
{
    int idx = blockIdx.x * blockDim.x + threadIdx.x;
    if (idx >= BATCH * EMH) return;
    int b = idx >> 8;        // EMH = 256
    int j = idx & (EMH - 1);
    eh[idx] = fmaxf(em[b] * W0[j] + b0[j], 0.f);
}

// logits = gate_h @ gate_W1 + gate_b1  (warp-per-row, shuffle reduce)
__global__ void logits_kernel(const float* __restrict__ gh, const float* __restrict__ W,
                              const float* __restrict__ b, float* __restrict__ logits)
{
    int warp = (blockIdx.x * blockDim.x + threadIdx.x) >> 5;
    int lane = threadIdx.x & 31;
    if (warp >= BATCH) return;
    const float* g = gh + warp * GH;
    float acc[GOUT];
#pragma unroll
    for (int j = 0; j < GOUT; j++) acc[j] = 0.f;
    for (int k = lane; k < GH; k += 32) {
        float gv = g[k];
        const float* wr = W + k * GOUT;
#pragma unroll
        for (int j = 0; j < GOUT; j++) acc[j] += gv * wr[j];
    }
#pragma unroll
    for (int j = 0; j < GOUT; j++) {
#pragma unroll
        for (int o = 16; o > 0; o >>= 1)
            acc[j] += __shfl_xor_sync(0xffffffffu, acc[j], o);
    }
    if (lane == 0) {
        float* dst = logits + warp * GOUT;
#pragma unroll
        for (int j = 0; j < GOUT; j++) dst[j] = acc[j] + b[j];
    }
}

// Routing: top-2 + softmax gates per module group (matches jax.lax.top_k ties)
__device__ __forceinline__ void route_m(const float* l, int m,
                                        float* g, float* oh, float* sm)
{
    float mx = l[0];
    for (int i = 1; i < m; i++) mx = fmaxf(mx, l[i]);
    float e[4], s = 0.f;
    for (int i = 0; i < m; i++) { e[i] = expf(l[i] - mx); s += e[i]; }
    float inv = 1.f / s;
    for (int i = 0; i < m; i++) sm[i] = e[i] * inv;
    int i1 = 0;
    for (int i = 1; i < m; i++) if (l[i] > l[i1]) i1 = i;
    int i2 = -1;
    for (int i = 0; i < m; i++) {
        if (i == i1) continue;
        if (i2 < 0 || l[i] > l[i2]) i2 = i;
    }
    float m2 = fmaxf(l[i1], l[i2]);
    float ea = expf(l[i1] - m2), eb = expf(l[i2] - m2);
    float si = 1.f / (ea + eb);
    g[i1] = ea * si; g[i2] = eb * si;
    oh[i1] = 1.f; oh[i2] = 1.f;
}

__global__ void routing_kernel(const float* __restrict__ logits, float* __restrict__ gdev,
                               float* __restrict__ og, float* __restrict__ ooh,
                               float* __restrict__ osm)
{
    int b = blockIdx.x * blockDim.x + threadIdx.x;
    if (b >= BATCH) return;
    float l[GOUT];
#pragma unroll
    for (int i = 0; i < GOUT; i++) l[i] = logits[b * GOUT + i];
    float g[GOUT], oh[GOUT], sm[GOUT];
#pragma unroll
    for (int i = 0; i < GOUT; i++) { g[i] = 0.f; oh[i] = 0.f; sm[i] = 0.f; }
    g[0] = 1.f; oh[0] = 1.f; sm[0] = 1.f;   // m=1 group
    route_m(l + 1, 2, g + 1, oh + 1, sm + 1);
    route_m(l + 3, 3, g + 3, oh + 3, sm + 3);
    route_m(l + 6, 4, g + 6, oh + 6, sm + 6);
#pragma unroll
    for (int i = 0; i < GOUT; i++) {
        gdev[b * GOUT + i] = g[i];
        og  [b * GOUT + i] = g[i];
        ooh [b * GOUT + i] = oh[i];
        osm [b * GOUT + i] = sm[i];
    }
}

// dst[b,:] = sum_t gates[b, goff+t] * o_t[b,:]   (float4 per thread)
__global__ void wsum_kernel(const float* __restrict__ gates, int goff, int nt,
                            const float* __restrict__ o0, const float* __restrict__ o1,
                            const float* __restrict__ o2, const float* __restrict__ o3,
                            float* __restrict__ dst)
{
    int idx = blockIdx.x * blockDim.x + threadIdx.x;    // float4 index
    if (idx >= BATCH * (HDIM / 4)) return;
    int b = idx / (HDIM / 4);
    const float* g = gates + b * GOUT + goff;
    float4 r = make_float4(0.f, 0.f, 0.f, 0.f);
    float w; float4 v;
    w = g[0]; v = ((const float4*)o0)[idx];
    r.x += w * v.x; r.y += w * v.y; r.z += w * v.z; r.w += w * v.w;
    if (nt > 1) {
        w = g[1]; v = ((const float4*)o1)[idx];
        r.x += w * v.x; r.y += w * v.y; r.z += w * v.z; r.w += w * v.w;
    }
    if (nt > 2) {
        w = g[2]; v = ((const float4*)o2)[idx];
        r.x += w * v.x; r.y += w * v.y; r.z += w * v.z; r.w += w * v.w;
    }
    if (nt > 3) {
        w = g[3]; v = ((const float4*)o3)[idx];
        r.x += w * v.x; r.y += w * v.y; r.z += w * v.z; r.w += w * v.w;
    }
    ((float4*)dst)[idx] = r;
}

// final = last_buf @ last_W + last_b   (N=18)
__global__ void final_kernel(const float* __restrict__ last, const float* __restrict__ W,
                             const float* __restrict__ b, float* __restrict__ out)
{
    int idx = blockIdx.x * blockDim.x + threadIdx.x;
    if (idx >= BATCH * OUTD) return;
    int row = idx / OUTD, o = idx % OUTD;
    const float4* lp = (const float4*)(last + row * HDIM);
    float s = 0.f;
    for (int k = 0; k < HDIM / 4; k++) {
        float4 v = lp[k];
        s += v.x * W[(4 * k + 0) * OUTD + o];
        s += v.y * W[(4 * k + 1) * OUTD + o];
        s += v.z * W[(4 * k + 2) * OUTD + o];
        s += v.w * W[(4 * k + 3) * OUTD + o];
    }
    out[idx] = s + b[o];
}

extern "C" void kernel_launch(void* const* d_in, const int* in_sizes, int n_in,
                              void* d_out, int out_size)
{
    const float* x        = (const float*)d_in[0];
    const float* em       = (const float*)d_in[1];
    const float* base_W0  = (const float*)d_in[2];
    const float* base_b0  = (const float*)d_in[3];
    const float* base_W1  = (const float*)d_in[4];
    const float* base_b1  = (const float*)d_in[5];
    const float* em_W0    = (const float*)d_in[6];
    const float* em_b0    = (const float*)d_in[7];
    const float* em_W1    = (const float*)d_in[8];
    const float* em_b1    = (const float*)d_in[9];
    const float* gate_W0  = (const float*)d_in[10];
    const float* gate_b0  = (const float*)d_in[11];
    const float* gate_W1  = (const float*)d_in[12];
    const float* gate_b1  = (const float*)d_in[13];
    const float* fc_W     = (const float*)d_in[14];
    const float* fc_b     = (const float*)d_in[15];
    const float* last_W   = (const float*)d_in[16];
    const float* last_b   = (const float*)d_in[17];
    float* out = (float*)d_out;

    float *h0, *base, *eh, *gin, *gh, *logits, *gates;
    float *o0, *o1, *o2, *o3, *inp, *last;
    cudaGetSymbolAddress((void**)&h0,   g_h0);
    cudaGetSymbolAddress((void**)&base, g_base);
    cudaGetSymbolAddress((void**)&eh,   g_eh);
    cudaGetSymbolAddress((void**)&gin,  g_gin);
    cudaGetSymbolAddress((void**)&gh,   g_gh);
    cudaGetSymbolAddress((void**)&logits, g_logits);
    cudaGetSymbolAddress((void**)&gates,  g_gates);
    cudaGetSymbolAddress((void**)&o0,  g_out0);
    cudaGetSymbolAddress((void**)&o1,  g_out1);
    cudaGetSymbolAddress((void**)&o2,  g_out2);
    cudaGetSymbolAddress((void**)&o3,  g_out3);
    cudaGetSymbolAddress((void**)&inp, g_inp);
    cudaGetSymbolAddress((void**)&last, g_last);

    const int OFF_G  = BATCH * OUTD;
    const int OFF_OH = OFF_G + BATCH * GOUT;
    const int OFF_SM = OFF_OH + BATCH * GOUT;

    const dim3 gridH (HDIM / 128, BATCH / 128);   // N=1024
    const dim3 gridGH(GH   / 128, BATCH / 128);   // N=512

    // 1) h0 = relu(x @ base_W0 + b0)
    sgemm2_kernel<false, true,  false><<<gridH, 256>>>(x, base_W0, base_b0, nullptr, h0, BATCH, HDIM, 64);
    // 2) base_out = h0 @ base_W1 + b1
    sgemm2_kernel<false, false, false><<<gridH, 256>>>(h0, base_W1, base_b1, nullptr, base, BATCH, HDIM, HDIM);
    // 3) eh = relu(em * em_W0 + em_b0)
    ehidden_kernel<<<(BATCH * EMH + 255) / 256, 256>>>(em, em_W0, em_b0, eh);
    // 4) gate_in = relu(eh @ em_W1 + em_b1) * base_out
    sgemm2_kernel<false, true,  true ><<<gridH, 256>>>(eh, em_W1, em_b1, base, gin, BATCH, HDIM, EMH);
    // 5) gate_h = relu(gate_in @ gate_W0 + gate_b0)
    sgemm2_kernel<false, true,  false><<<gridGH, 256>>>(gin, gate_W0, gate_b0, nullptr, gh, BATCH, GH, HDIM);
    // 6) logits
    logits_kernel<<<(BATCH * 32 + 255) / 256, 256>>>(gh, gate_W1, gate_b1, logits);
    // 7) routing -> gates + (gates, onehot, soft) outputs
    routing_kernel<<<(BATCH + 255) / 256, 256>>>(logits, gates, out + OFF_G, out + OFF_OH, out + OFF_SM);
    // 8) out0 = relu(relu(base_out) @ fc_W0 + fc_b0)
    sgemm2_kernel<true,  true,  false><<<gridH, 256>>>(base, fc_W, fc_b, nullptr, o0, BATCH, HDIM, HDIM);
    // 9) out1 = relu(out0 @ fc_W1 + fc_b1)   (gate for step1 is identically 1)
    sgemm2_kernel<false, true,  false><<<gridH, 256>>>(o0, fc_W + 1 * HDIM * HDIM, fc_b + 1 * HDIM, nullptr, o1, BATCH, HDIM, HDIM);
    // 10) inp = g1*out0 + g2*out1 ; out2 = relu(inp @ fc_W2 + fc_b2)
    wsum_kernel<<<(BATCH * HDIM / 4 + 255) / 256, 256>>>(gates, 1, 2, o0, o1, nullptr, nullptr, inp);
    sgemm2_kernel<false, true,  false><<<gridH, 256>>>(inp, fc_W + 2 * HDIM * HDIM, fc_b + 2 * HDIM, nullptr, o2, BATCH, HDIM, HDIM);
    // 11) inp = g3*out0 + g4*out1 + g5*out2 ; out3 = relu(inp @ fc_W3 + fc_b3)
    wsum_kernel<<<(BATCH * HDIM / 4 + 255) / 256, 256>>>(gates, 3, 3, o0, o1, o2, nullptr, inp);
    sgemm2_kernel<false, true,  false><<<gridH, 256>>>(inp, fc_W + 3 * HDIM * HDIM, fc_b + 3 * HDIM, nullptr, o3, BATCH, HDIM, HDIM);
    // 12) last = sum g6..g9 * out0..3 ; final = last @ last_W + last_b
    wsum_kernel<<<(BATCH * HDIM / 4 + 255) / 256, 256>>>(gates, 6, 4, o0, o1, o2, o3, last);
    final_kernel<<<(BATCH * OUTD + 255) / 256, 256>>>(last, last_W, last_b, out);
}

// round 3
// speedup vs baseline: 1.0273x; 1.0273x over previous
#include <cuda_runtime.h>
#include <math.h>

#define BATCH 8192
#define HDIM  1024
#define GH    512
#define EMH   256
#define OUTD  18
#define GOUT  10

typedef unsigned long long u64;

// -------- scratch (device globals: allocation-free) --------
__device__ float g_h0  [BATCH*HDIM];
__device__ float g_base[BATCH*HDIM];
__device__ float g_eh  [BATCH*EMH];
__device__ float g_gin [BATCH*HDIM];
__device__ float g_gh  [BATCH*GH];
__device__ float g_logits[BATCH*GOUT];
__device__ float g_gates [BATCH*GOUT];
__device__ float g_out0[BATCH*HDIM];
__device__ float g_out1[BATCH*HDIM];
__device__ float g_out2[BATCH*HDIM];
__device__ float g_out3[BATCH*HDIM];
__device__ float g_inp [BATCH*HDIM];
__device__ float g_last[BATCH*HDIM];

// packed fp32x2 fma: d = a*b + d (lanewise, exact fp32)
__device__ __forceinline__ void ffma2(u64 &d, u64 a, u64 b) {
    asm("fma.rn.f32x2 %0, %1, %2, %0;" : "+l"(d) : "l"(a), "l"(b));
}
__device__ __forceinline__ u64 d2u(double d) { return __double_as_longlong(d); }
__device__ __forceinline__ float u_lo(u64 v) { return __int_as_float((int)(unsigned)v); }
__device__ __forceinline__ float u_hi(u64 v) { return __int_as_float((int)(unsigned)(v >> 32)); }
__device__ __forceinline__ void relu4(float4 &v) {
    v.x = fmaxf(v.x, 0.f); v.y = fmaxf(v.y, 0.f);
    v.z = fmaxf(v.z, 0.f); v.w = fmaxf(v.w, 0.f);
}

// =====================================================================
// Packed-FFMA2 tiled SGEMM: C = epi( op(A) @ B + bias )
// BM=BN=128, BK=8, 8x8 per thread (8x4 f32x2 pairs), 256 threads,
// min 2 CTAs/SM (128-reg cap) so LDS latency is hidden by warp supply.
// A tile stored lane-duplicated in shared -> f32x2 A operands are
// direct LDS; B pairs naturally contiguous.
// Requires M%128==0, N%128==0, K%8==0 (true for all shapes here).
// =====================================================================
template<bool RELU_A, bool RELU_C, bool MUL_C>
__global__ __launch_bounds__(256, 2)
void sgemm2_kernel(const float* __restrict__ A, const float* __restrict__ Bm,
                   const float* __restrict__ bias, const float* __restrict__ Cmul,
                   float* __restrict__ C, int M, int N, int K)
{
    __shared__ float Asd[8][256];   // duplicated: Asd[k][2m]=Asd[k][2m+1]=A[m,k]
    __shared__ float Bs [8][128];
    const int tid = threadIdx.x;
    const int bm = blockIdx.y * 128;
    const int bn = blockIdx.x * 128;

    const int arow = tid >> 1;          // 0..127
    const int acol = (tid & 1) << 2;    // 0 or 4
    const int brow = tid >> 5;          // 0..7
    const int bcol = (tid & 31) << 2;   // 0..124
    const int tx = (tid & 15) << 3;     // col offset within tile (8 cols = 4 pairs)
    const int ty = (tid >> 4) << 3;     // row offset within tile

    u64 acc[8][4];
#pragma unroll
    for (int i = 0; i < 8; i++)
#pragma unroll
        for (int j = 0; j < 4; j++) acc[i][j] = 0ull;

    const float* Ap = A + (bm + arow) * K + acol;
    const float* Bp = Bm + brow * N + bn + bcol;

    // prefetch first slab into registers
    float4 av = *(const float4*)Ap;
    if (RELU_A) relu4(av);
    float4 bv = *(const float4*)Bp;

    for (int k0 = 0; k0 < K; k0 += 8) {
        // stage current slab (A duplicated via float2 stores)
        *(float2*)&Asd[acol + 0][2 * arow] = make_float2(av.x, av.x);
        *(float2*)&Asd[acol + 1][2 * arow] = make_float2(av.y, av.y);
        *(float2*)&Asd[acol + 2][2 * arow] = make_float2(av.z, av.z);
        *(float2*)&Asd[acol + 3][2 * arow] = make_float2(av.w, av.w);
        *(float4*)&Bs[brow][bcol] = bv;
        __syncthreads();

        // prefetch next slab (overlaps compute)
        if (k0 + 8 < K) {
            av = *(const float4*)(Ap + k0 + 8);
            if (RELU_A) relu4(av);
            bv = *(const float4*)(Bp + (k0 + 8) * N);
        }

#pragma unroll
        for (int k = 0; k < 8; k++) {
            const double2 b01 = *(const double2*)&Bs[k][tx];
            const double2 b23 = *(const double2*)&Bs[k][tx + 4];
            const u64 bp0 = d2u(b01.x), bp1 = d2u(b01.y);
            const u64 bp2 = d2u(b23.x), bp3 = d2u(b23.y);
#pragma unroll
            for (int ih = 0; ih < 4; ih++) {
                const double2 aa = *(const double2*)&Asd[k][2 * (ty + 2 * ih)];
                const u64 a0 = d2u(aa.x), a1 = d2u(aa.y);
                ffma2(acc[2 * ih + 0][0], a0, bp0);
                ffma2(acc[2 * ih + 0][1], a0, bp1);
                ffma2(acc[2 * ih + 0][2], a0, bp2);
                ffma2(acc[2 * ih + 0][3], a0, bp3);
                ffma2(acc[2 * ih + 1][0], a1, bp0);
                ffma2(acc[2 * ih + 1][1], a1, bp1);
                ffma2(acc[2 * ih + 1][2], a1, bp2);
                ffma2(acc[2 * ih + 1][3], a1, bp3);
            }
        }
        __syncthreads();
    }

#pragma unroll
    for (int i = 0; i < 8; i++) {
        const int row = bm + ty + i;
        float c[8];
#pragma unroll
        for (int j = 0; j < 4; j++) {
            c[2 * j + 0] = u_lo(acc[i][j]);
            c[2 * j + 1] = u_hi(acc[i][j]);
        }
#pragma unroll
        for (int j = 0; j < 8; j += 4) {
            const int col = bn + tx + j;
            float4 cv;
            cv.x = c[j + 0] + bias[col + 0];
            cv.y = c[j + 1] + bias[col + 1];
            cv.z = c[j + 2] + bias[col + 2];
            cv.w = c[j + 3] + bias[col + 3];
            if (RELU_C) relu4(cv);
            if (MUL_C) {
                const float4 mv = *(const float4*)(Cmul + row * N + col);
                cv.x *= mv.x; cv.y *= mv.y; cv.z *= mv.z; cv.w *= mv.w;
            }
            *(float4*)(C + row * N + col) = cv;
        }
    }
}

// em hidden: eh[b,j] = relu(em[b]*em_W0[j] + em_b0[j])
__global__ void ehidden_kernel(const float* __restrict__ em, const float* __restrict__ W0,
                               const float* __restrict__ b0, float* __restrict__ eh)
{
    int idx = blockIdx.x * blockDim.x + threadIdx.x;
    if (idx >= BATCH * EMH) return;
    int b = idx >> 8;        // EMH = 256
    int j = idx & (EMH - 1);
    eh[idx] = fmaxf(em[b] * W0[j] + b0[j], 0.f);
}

// logits = gate_h @ gate_W1 + gate_b1  (warp-per-row, shuffle reduce)
__global__ void logits_kernel(const float* __restrict__ gh, const float* __restrict__ W,
                              const float* __restrict__ b, float* __restrict__ logits)
{
    int warp = (blockIdx.x * blockDim.x + threadIdx.x) >> 5;
    int lane = threadIdx.x & 31;
    if (warp >= BATCH) return;
    const float* g = gh + warp * GH;
    float acc[GOUT];
#pragma unroll
    for (int j = 0; j < GOUT; j++) acc[j] = 0.f;
    for (int k = lane; k < GH; k += 32) {
        float gv = g[k];
        const float* wr = W + k * GOUT;
#pragma unroll
        for (int j = 0; j < GOUT; j++) acc[j] += gv * wr[j];
    }
#pragma unroll
    for (int j = 0; j < GOUT; j++) {
#pragma unroll
        for (int o = 16; o > 0; o >>= 1)
            acc[j] += __shfl_xor_sync(0xffffffffu, acc[j], o);
    }
    if (lane == 0) {
        float* dst = logits + warp * GOUT;
#pragma unroll
        for (int j = 0; j < GOUT; j++) dst[j] = acc[j] + b[j];
    }
}

// Routing: top-2 + softmax gates per module group (matches jax.lax.top_k ties)
__device__ __forceinline__ void route_m(const float* l, int m,
                                        float* g, float* oh, float* sm)
{
    float mx = l[0];
    for (int i = 1; i < m; i++) mx = fmaxf(mx, l[i]);
    float e[4], s = 0.f;
    for (int i = 0; i < m; i++) { e[i] = expf(l[i] - mx); s += e[i]; }
    float inv = 1.f / s;
    for (int i = 0; i < m; i++) sm[i] = e[i] * inv;
    int i1 = 0;
    for (int i = 1; i < m; i++) if (l[i] > l[i1]) i1 = i;
    int i2 = -1;
    for (int i = 0; i < m; i++) {
        if (i == i1) continue;
        if (i2 < 0 || l[i] > l[i2]) i2 = i;
    }
    float m2 = fmaxf(l[i1], l[i2]);
    float ea = expf(l[i1] - m2), eb = expf(l[i2] - m2);
    float si = 1.f / (ea + eb);
    g[i1] = ea * si; g[i2] = eb * si;
    oh[i1] = 1.f; oh[i2] = 1.f;
}

__global__ void routing_kernel(const float* __restrict__ logits, float* __restrict__ gdev,
                               float* __restrict__ og, float* __restrict__ ooh,
                               float* __restrict__ osm)
{
    int b = blockIdx.x * blockDim.x + threadIdx.x;
    if (b >= BATCH) return;
    float l[GOUT];
#pragma unroll
    for (int i = 0; i < GOUT; i++) l[i] = logits[b * GOUT + i];
    float g[GOUT], oh[GOUT], sm[GOUT];
#pragma unroll
    for (int i = 0; i < GOUT; i++) { g[i] = 0.f; oh[i] = 0.f; sm[i] = 0.f; }
    g[0] = 1.f; oh[0] = 1.f; sm[0] = 1.f;   // m=1 group
    route_m(l + 1, 2, g + 1, oh + 1, sm + 1);
    route_m(l + 3, 3, g + 3, oh + 3, sm + 3);
    route_m(l + 6, 4, g + 6, oh + 6, sm + 6);
#pragma unroll
    for (int i = 0; i < GOUT; i++) {
        gdev[b * GOUT + i] = g[i];
        og  [b * GOUT + i] = g[i];
        ooh [b * GOUT + i] = oh[i];
        osm [b * GOUT + i] = sm[i];
    }
}

// dst[b,:] = sum_t gates[b, goff+t] * o_t[b,:]   (float4 per thread)
__global__ void wsum_kernel(const float* __restrict__ gates, int goff, int nt,
                            const float* __restrict__ o0, const float* __restrict__ o1,
                            const float* __restrict__ o2, const float* __restrict__ o3,
                            float* __restrict__ dst)
{
    int idx = blockIdx.x * blockDim.x + threadIdx.x;    // float4 index
    if (idx >= BATCH * (HDIM / 4)) return;
    int b = idx / (HDIM / 4);
    const float* g = gates + b * GOUT + goff;
    float4 r = make_float4(0.f, 0.f, 0.f, 0.f);
    float w; float4 v;
    w = g[0]; v = ((const float4*)o0)[idx];
    r.x += w * v.x; r.y += w * v.y; r.z += w * v.z; r.w += w * v.w;
    if (nt > 1) {
        w = g[1]; v = ((const float4*)o1)[idx];
        r.x += w * v.x; r.y += w * v.y; r.z += w * v.z; r.w += w * v.w;
    }
    if (nt > 2) {
        w = g[2]; v = ((const float4*)o2)[idx];
        r.x += w * v.x; r.y += w * v.y; r.z += w * v.z; r.w += w * v.w;
    }
    if (nt > 3) {
        w = g[3]; v = ((const float4*)o3)[idx];
        r.x += w * v.x; r.y += w * v.y; r.z += w * v.z; r.w += w * v.w;
    }
    ((float4*)dst)[idx] = r;
}

// final = last_buf @ last_W + last_b   (N=18)
__global__ void final_kernel(const float* __restrict__ last, const float* __restrict__ W,
                             const float* __restrict__ b, float* __restrict__ out)
{
    int idx = blockIdx.x * blockDim.x + threadIdx.x;
    if (idx >= BATCH * OUTD) return;
    int row = idx / OUTD, o = idx % OUTD;
    const float4* lp = (const float4*)(last + row * HDIM);
    float s = 0.f;
    for (int k = 0; k < HDIM / 4; k++) {
        float4 v = lp[k];
        s += v.x * W[(4 * k + 0) * OUTD + o];
        s += v.y * W[(4 * k + 1) * OUTD + o];
        s += v.z * W[(4 * k + 2) * OUTD + o];
        s += v.w * W[(4 * k + 3) * OUTD + o];
    }
    out[idx] = s + b[o];
}

extern "C" void kernel_launch(void* const* d_in, const int* in_sizes, int n_in,
                              void* d_out, int out_size)
{
    const float* x        = (const float*)d_in[0];
    const float* em       = (const float*)d_in[1];
    const float* base_W0  = (const float*)d_in[2];
    const float* base_b0  = (const float*)d_in[3];
    const float* base_W1  = (const float*)d_in[4];
    const float* base_b1  = (const float*)d_in[5];
    const float* em_W0    = (const float*)d_in[6];
    const float* em_b0    = (const float*)d_in[7];
    const float* em_W1    = (const float*)d_in[8];
    const float* em_b1    = (const float*)d_in[9];
    const float* gate_W0  = (const float*)d_in[10];
    const float* gate_b0  = (const float*)d_in[11];
    const float* gate_W1  = (const float*)d_in[12];
    const float* gate_b1  = (const float*)d_in[13];
    const float* fc_W     = (const float*)d_in[14];
    const float* fc_b     = (const float*)d_in[15];
    const float* last_W   = (const float*)d_in[16];
    const float* last_b   = (const float*)d_in[17];
    float* out = (float*)d_out;

    float *h0, *base, *eh, *gin, *gh, *logits, *gates;
    float *o0, *o1, *o2, *o3, *inp, *last;
    cudaGetSymbolAddress((void**)&h0,   g_h0);
    cudaGetSymbolAddress((void**)&base, g_base);
    cudaGetSymbolAddress((void**)&eh,   g_eh);
    cudaGetSymbolAddress((void**)&gin,  g_gin);
    cudaGetSymbolAddress((void**)&gh,   g_gh);
    cudaGetSymbolAddress((void**)&logits, g_logits);
    cudaGetSymbolAddress((void**)&gates,  g_gates);
    cudaGetSymbolAddress((void**)&o0,  g_out0);
    cudaGetSymbolAddress((void**)&o1,  g_out1);
    cudaGetSymbolAddress((void**)&o2,  g_out2);
    cudaGetSymbolAddress((void**)&o3,  g_out3);
    cudaGetSymbolAddress((void**)&inp, g_inp);
    cudaGetSymbolAddress((void**)&last, g_last);

    const int OFF_G  = BATCH * OUTD;
    const int OFF_OH = OFF_G + BATCH * GOUT;
    const int OFF_SM = OFF_OH + BATCH * GOUT;

    const dim3 gridH (HDIM / 128, BATCH / 128);   // N=1024
    const dim3 gridGH(GH   / 128, BATCH / 128);   // N=512

    // 1) h0 = relu(x @ base_W0 + b0)
    sgemm2_kernel<false, true,  false><<<gridH, 256>>>(x, base_W0, base_b0, nullptr, h0, BATCH, HDIM, 64);
    // 2) base_out = h0 @ base_W1 + b1
    sgemm2_kernel<false, false, false><<<gridH, 256>>>(h0, base_W1, base_b1, nullptr, base, BATCH, HDIM, HDIM);
    // 3) eh = relu(em * em_W0 + em_b0)
    ehidden_kernel<<<(BATCH * EMH + 255) / 256, 256>>>(em, em_W0, em_b0, eh);
    // 4) gate_in = relu(eh @ em_W1 + em_b1) * base_out
    sgemm2_kernel<false, true,  true ><<<gridH, 256>>>(eh, em_W1, em_b1, base, gin, BATCH, HDIM, EMH);
    // 5) gate_h = relu(gate_in @ gate_W0 + gate_b0)
    sgemm2_kernel<false, true,  false><<<gridGH, 256>>>(gin, gate_W0, gate_b0, nullptr, gh, BATCH, GH, HDIM);
    // 6) logits
    logits_kernel<<<(BATCH * 32 + 255) / 256, 256>>>(gh, gate_W1, gate_b1, logits);
    // 7) routing -> gates + (gates, onehot, soft) outputs
    routing_kernel<<<(BATCH + 255) / 256, 256>>>(logits, gates, out + OFF_G, out + OFF_OH, out + OFF_SM);
    // 8) out0 = relu(relu(base_out) @ fc_W0 + fc_b0)
    sgemm2_kernel<true,  true,  false><<<gridH, 256>>>(base, fc_W, fc_b, nullptr, o0, BATCH, HDIM, HDIM);
    // 9) out1 = relu(out0 @ fc_W1 + fc_b1)   (gate for step1 is identically 1)
    sgemm2_kernel<false, true,  false><<<gridH, 256>>>(o0, fc_W + 1 * HDIM * HDIM, fc_b + 1 * HDIM, nullptr, o1, BATCH, HDIM, HDIM);
    // 10) inp = g1*out0 + g2*out1 ; out2 = relu(inp @ fc_W2 + fc_b2)
    wsum_kernel<<<(BATCH * HDIM / 4 + 255) / 256, 256>>>(gates, 1, 2, o0, o1, nullptr, nullptr, inp);
    sgemm2_kernel<false, true,  false><<<gridH, 256>>>(inp, fc_W + 2 * HDIM * HDIM, fc_b + 2 * HDIM, nullptr, o2, BATCH, HDIM, HDIM);
    // 11) inp = g3*out0 + g4*out1 + g5*out2 ; out3 = relu(inp @ fc_W3 + fc_b3)
    wsum_kernel<<<(BATCH * HDIM / 4 + 255) / 256, 256>>>(gates, 3, 3, o0, o1, o2, nullptr, inp);
    sgemm2_kernel<false, true,  false><<<gridH, 256>>>(inp, fc_W + 3 * HDIM * HDIM, fc_b + 3 * HDIM, nullptr, o3, BATCH, HDIM, HDIM);
    // 12) last = sum g6..g9 * out0..3 ; final = last @ last_W + last_b
    wsum_kernel<<<(BATCH * HDIM / 4 + 255) / 256, 256>>>(gates, 6, 4, o0, o1, o2, o3, last);
    final_kernel<<<(BATCH * OUTD + 255) / 256, 256>>>(last, last_W, last_b, out);
}

// round 5
// speedup vs baseline: 1.5894x; 1.5472x over previous
#include <cuda_runtime.h>
#include <cuda_bf16.h>
#include <math.h>
#include <stdint.h>

#define BATCH 8192
#define HDIM  1024
#define GH    512
#define EMH   256
#define OUTD  18
#define GOUT  10

typedef unsigned long long u64;

// -------- scratch (device globals: allocation-free) --------
__device__ float g_h0  [BATCH*HDIM];
__device__ float g_base[BATCH*HDIM];
__device__ float g_eh  [BATCH*EMH];
__device__ float g_gin [BATCH*HDIM];
__device__ float g_gh  [BATCH*GH];
__device__ float g_logits[BATCH*GOUT];
__device__ float g_gates [BATCH*GOUT];
__device__ float g_out0[BATCH*HDIM];
__device__ float g_out1[BATCH*HDIM];
__device__ float g_out2[BATCH*HDIM];
__device__ float g_out3[BATCH*HDIM];
__device__ float g_inp [BATCH*HDIM];
__device__ float g_last[BATCH*HDIM];
__device__ __nv_bfloat16 g_wbh[4*HDIM*HDIM];   // fc weights: [mod][N][K] bf16 hi
__device__ __nv_bfloat16 g_wbl[4*HDIM*HDIM];   // fc weights: [mod][N][K] bf16 lo

__device__ __forceinline__ void relu4(float4 &v) {
    v.x = fmaxf(v.x, 0.f); v.y = fmaxf(v.y, 0.f);
    v.z = fmaxf(v.z, 0.f); v.w = fmaxf(v.w, 0.f);
}

// =====================================================================
// fp32 scalar SGEMM (R1 version — gating path, precision-critical)
// =====================================================================
template<bool RELU_A, bool RELU_C, bool MUL_C>
__global__ __launch_bounds__(256)
void sgemm_kernel(const float* __restrict__ A, const float* __restrict__ Bm,
                  const float* __restrict__ bias, const float* __restrict__ Cmul,
                  float* __restrict__ C, int M, int N, int K)
{
    __shared__ float As[8][128];
    __shared__ float Bs[8][128];
    const int tid = threadIdx.x;
    const int bm = blockIdx.y * 128;
    const int bn = blockIdx.x * 128;

    const int arow = tid >> 1;
    const int acol = (tid & 1) << 2;
    const int brow = tid >> 5;
    const int bcol = (tid & 31) << 2;
    const int tx = (tid & 15) << 3;
    const int ty = (tid >> 4) << 3;

    float acc[8][8];
#pragma unroll
    for (int i = 0; i < 8; i++)
#pragma unroll
        for (int j = 0; j < 8; j++) acc[i][j] = 0.f;

    const float* Ap = A + (bm + arow) * K + acol;
    const float* Bp = Bm + brow * N + bn + bcol;

    for (int k0 = 0; k0 < K; k0 += 8) {
        float4 av = *(const float4*)(Ap + k0);
        if (RELU_A) relu4(av);
        As[acol + 0][arow] = av.x;
        As[acol + 1][arow] = av.y;
        As[acol + 2][arow] = av.z;
        As[acol + 3][arow] = av.w;
        *(float4*)&Bs[brow][bcol] = *(const float4*)(Bp + k0 * N);
        __syncthreads();
#pragma unroll
        for (int k = 0; k < 8; k++) {
            float ra[8], rb[8];
#pragma unroll
            for (int i = 0; i < 8; i++) ra[i] = As[k][ty + i];
#pragma unroll
            for (int j = 0; j < 8; j++) rb[j] = Bs[k][tx + j];
#pragma unroll
            for (int i = 0; i < 8; i++)
#pragma unroll
                for (int j = 0; j < 8; j++) acc[i][j] += ra[i] * rb[j];
        }
        __syncthreads();
    }

#pragma unroll
    for (int i = 0; i < 8; i++) {
        const int row = bm + ty + i;
#pragma unroll
        for (int j = 0; j < 8; j += 4) {
            const int col = bn + tx + j;
            float4 c;
            c.x = acc[i][j + 0] + bias[col + 0];
            c.y = acc[i][j + 1] + bias[col + 1];
            c.z = acc[i][j + 2] + bias[col + 2];
            c.w = acc[i][j + 3] + bias[col + 3];
            if (RELU_C) relu4(c);
            if (MUL_C) {
                const float4 mv = *(const float4*)(Cmul + row * N + col);
                c.x *= mv.x; c.y *= mv.y; c.z *= mv.z; c.w *= mv.w;
            }
            *(float4*)(C + row * N + col) = c;
        }
    }
}

// =====================================================================
// bf16x3 split tensor-core GEMM (mma.sync.m16n8k16, baseline PTX):
//   C = relu( op(A) @ Wt^T + bias ),  A fp32 [8192,K], Wt bf16 hi/lo [N][K]
// Error ~2^-18 per product (Ah*Bh + Ah*Bl + Al*Bh; Al*Bl dropped).
// CTA 128x128, K-slab 32, 8 warps (4 M x 2 N), warp tile 32x64.
// =====================================================================
#define TCK 32
#define STR 40   // smem row stride in bf16 elems (conflict-free for frag map)

__device__ __forceinline__ void mma16816(float c[4], const uint32_t a[4],
                                         const uint32_t b[2]) {
    asm("mma.sync.aligned.m16n8k16.row.col.f32.bf16.bf16.f32 "
        "{%0,%1,%2,%3}, {%4,%5,%6,%7}, {%8,%9}, {%0,%1,%2,%3};"
        : "+f"(c[0]), "+f"(c[1]), "+f"(c[2]), "+f"(c[3])
        : "r"(a[0]), "r"(a[1]), "r"(a[2]), "r"(a[3]), "r"(b[0]), "r"(b[1]));
}

template<bool RELU_A>
__global__ __launch_bounds__(256, 2)
void tc_gemm_kernel(const float* __restrict__ A,
                    const __nv_bfloat16* __restrict__ Wh,
                    const __nv_bfloat16* __restrict__ Wl,
                    const float* __restrict__ bias, float* __restrict__ C)
{
    __shared__ uint16_t sAh[128 * STR];
    __shared__ uint16_t sAl[128 * STR];
    __shared__ uint16_t sBh[128 * STR];
    __shared__ uint16_t sBl[128 * STR];

    const int K = HDIM, N = HDIM;
    const int tid  = threadIdx.x;
    const int wid  = tid >> 5;
    const int lane = tid & 31;
    const int g = lane >> 2;         // 0..7
    const int t = lane & 3;          // 0..3
    const int warp_m = wid & 3;      // 0..3 -> 32-row band
    const int warp_n = wid >> 2;     // 0..1 -> 64-col band
    const int bm = blockIdx.y * 128;
    const int bn = blockIdx.x * 128;

    // staging map: 2 threads per row, 16 elems each
    const int srow = tid >> 1;
    const int kh   = (tid & 1) * 16;

    float acc[2][8][4];
#pragma unroll
    for (int mt = 0; mt < 2; mt++)
#pragma unroll
        for (int nt = 0; nt < 8; nt++)
#pragma unroll
            for (int e = 0; e < 4; e++) acc[mt][nt][e] = 0.f;

    const float* Ap = A + (u64)(bm + srow) * K + kh;
    const __nv_bfloat16* Bhp = Wh + (u64)(bn + srow) * K + kh;
    const __nv_bfloat16* Blp = Wl + (u64)(bn + srow) * K + kh;
    const int sbase = srow * STR + kh;

    for (int s = 0; s < K / TCK; s++) {
        // ---- stage A (fp32 -> bf16 hi/lo) ----
        float4 f[4];
#pragma unroll
        for (int i = 0; i < 4; i++) {
            f[i] = *(const float4*)(Ap + s * TCK + 4 * i);
            if (RELU_A) relu4(f[i]);
        }
        const float* fe = (const float*)f;
#pragma unroll
        for (int i = 0; i < 8; i++) {
            float v0 = fe[2 * i], v1 = fe[2 * i + 1];
            __nv_bfloat16 h0 = __float2bfloat16(v0);
            __nv_bfloat16 h1 = __float2bfloat16(v1);
            __nv_bfloat16 l0 = __float2bfloat16(v0 - __bfloat162float(h0));
            __nv_bfloat16 l1 = __float2bfloat16(v1 - __bfloat162float(h1));
            uint32_t ph = (uint32_t)__bfloat16_as_ushort(h0)
                        | ((uint32_t)__bfloat16_as_ushort(h1) << 16);
            uint32_t pl = (uint32_t)__bfloat16_as_ushort(l0)
                        | ((uint32_t)__bfloat16_as_ushort(l1) << 16);
            *(uint32_t*)&sAh[sbase + 2 * i] = ph;
            *(uint32_t*)&sAl[sbase + 2 * i] = pl;
        }
        // ---- stage B (bf16 direct copy) ----
        {
            const uint4* bh4 = (const uint4*)(Bhp + s * TCK);
            const uint4* bl4 = (const uint4*)(Blp + s * TCK);
            uint4 u0 = bh4[0], u1 = bh4[1];
            uint4 v0 = bl4[0], v1 = bl4[1];
            uint32_t* dh = (uint32_t*)&sBh[sbase];
            uint32_t* dl = (uint32_t*)&sBl[sbase];
            dh[0] = u0.x; dh[1] = u0.y; dh[2] = u0.z; dh[3] = u0.w;
            dh[4] = u1.x; dh[5] = u1.y; dh[6] = u1.z; dh[7] = u1.w;
            dl[0] = v0.x; dl[1] = v0.y; dl[2] = v0.z; dl[3] = v0.w;
            dl[4] = v1.x; dl[5] = v1.y; dl[6] = v1.z; dl[7] = v1.w;
        }
        __syncthreads();

        // ---- compute: 2 k16 steps ----
#pragma unroll
        for (int kk = 0; kk < TCK; kk += 16) {
            uint32_t ah[2][4], al[2][4];
#pragma unroll
            for (int mt = 0; mt < 2; mt++) {
                const int r0 = (warp_m * 32 + mt * 16 + g) * STR + kk + t * 2;
                const int r1 = r0 + 8 * STR;
                ah[mt][0] = *(const uint32_t*)&sAh[r0];
                ah[mt][1] = *(const uint32_t*)&sAh[r1];
                ah[mt][2] = *(const uint32_t*)&sAh[r0 + 8];
                ah[mt][3] = *(const uint32_t*)&sAh[r1 + 8];
                al[mt][0] = *(const uint32_t*)&sAl[r0];
                al[mt][1] = *(const uint32_t*)&sAl[r1];
                al[mt][2] = *(const uint32_t*)&sAl[r0 + 8];
                al[mt][3] = *(const uint32_t*)&sAl[r1 + 8];
            }
#pragma unroll
            for (int nt = 0; nt < 8; nt++) {
                const int nb = (warp_n * 64 + nt * 8 + g) * STR + kk + t * 2;
                uint32_t bh[2], bl[2];
                bh[0] = *(const uint32_t*)&sBh[nb];
                bh[1] = *(const uint32_t*)&sBh[nb + 8];
                bl[0] = *(const uint32_t*)&sBl[nb];
                bl[1] = *(const uint32_t*)&sBl[nb + 8];
#pragma unroll
                for (int mt = 0; mt < 2; mt++) {
                    mma16816(acc[mt][nt], ah[mt], bh);
                    mma16816(acc[mt][nt], ah[mt], bl);
                    mma16816(acc[mt][nt], al[mt], bh);
                }
            }
        }
        __syncthreads();
    }

    // ---- epilogue: bias + relu, fp32 out ----
#pragma unroll
    for (int mt = 0; mt < 2; mt++) {
#pragma unroll
        for (int nt = 0; nt < 8; nt++) {
            const int row = bm + warp_m * 32 + mt * 16 + g;
            const int col = bn + warp_n * 64 + nt * 8 + t * 2;
            const float b0 = bias[col], b1 = bias[col + 1];
            float2 v0, v1;
            v0.x = fmaxf(acc[mt][nt][0] + b0, 0.f);
            v0.y = fmaxf(acc[mt][nt][1] + b1, 0.f);
            v1.x = fmaxf(acc[mt][nt][2] + b0, 0.f);
            v1.y = fmaxf(acc[mt][nt][3] + b1, 0.f);
            *(float2*)(C + (u64)row * N + col)       = v0;
            *(float2*)(C + (u64)(row + 8) * N + col) = v1;
        }
    }
}

// transpose + bf16-split fc_W: [mod][K][N] fp32 -> [mod][N][K] bf16 hi/lo
__global__ void transpose_split_kernel(const float* __restrict__ W,
                                       __nv_bfloat16* __restrict__ Wh,
                                       __nv_bfloat16* __restrict__ Wl)
{
    __shared__ float tile[32][33];
    const int mod = blockIdx.z;
    const float* Wm = W + (u64)mod * HDIM * HDIM;
    __nv_bfloat16* Whm = Wh + (u64)mod * HDIM * HDIM;
    __nv_bfloat16* Wlm = Wl + (u64)mod * HDIM * HDIM;
    const int k0 = blockIdx.y * 32, n0 = blockIdx.x * 32;
    const int tx = threadIdx.x, ty = threadIdx.y;
#pragma unroll
    for (int i = 0; i < 32; i += 8)
        tile[ty + i][tx] = Wm[(u64)(k0 + ty + i) * HDIM + n0 + tx];
    __syncthreads();
#pragma unroll
    for (int i = 0; i < 32; i += 8) {
        float v = tile[tx][ty + i];
        __nv_bfloat16 h = __float2bfloat16(v);
        __nv_bfloat16 l = __float2bfloat16(v - __bfloat162float(h));
        Whm[(u64)(n0 + ty + i) * HDIM + k0 + tx] = h;
        Wlm[(u64)(n0 + ty + i) * HDIM + k0 + tx] = l;
    }
}

// em hidden: eh[b,j] = relu(em[b]*em_W0[j] + em_b0[j])
__global__ void ehidden_kernel(const float* __restrict__ em, const float* __restrict__ W0,
                               const float* __restrict__ b0, float* __restrict__ eh)
{
    int idx = blockIdx.x * blockDim.x + threadIdx.x;
    if (idx >= BATCH * EMH) return;
    int b = idx >> 8;
    int j = idx & (EMH - 1);
    eh[idx] = fmaxf(em[b] * W0[j] + b0[j], 0.f);
}

// logits = gate_h @ gate_W1 + gate_b1  (warp-per-row, shuffle reduce)
__global__ void logits_kernel(const float* __restrict__ gh, const float* __restrict__ W,
                              const float* __restrict__ b, float* __restrict__ logits)
{
    int warp = (blockIdx.x * blockDim.x + threadIdx.x) >> 5;
    int lane = threadIdx.x & 31;
    if (warp >= BATCH) return;
    const float* g = gh + warp * GH;
    float acc[GOUT];
#pragma unroll
    for (int j = 0; j < GOUT; j++) acc[j] = 0.f;
    for (int k = lane; k < GH; k += 32) {
        float gv = g[k];
        const float* wr = W + k * GOUT;
#pragma unroll
        for (int j = 0; j < GOUT; j++) acc[j] += gv * wr[j];
    }
#pragma unroll
    for (int j = 0; j < GOUT; j++) {
#pragma unroll
        for (int o = 16; o > 0; o >>= 1)
            acc[j] += __shfl_xor_sync(0xffffffffu, acc[j], o);
    }
    if (lane == 0) {
        float* dst = logits + warp * GOUT;
#pragma unroll
        for (int j = 0; j < GOUT; j++) dst[j] = acc[j] + b[j];
    }
}

// Routing: top-2 + softmax gates per module group (matches jax.lax.top_k ties)
__device__ __forceinline__ void route_m(const float* l, int m,
                                        float* g, float* oh, float* sm)
{
    float mx = l[0];
    for (int i = 1; i < m; i++) mx = fmaxf(mx, l[i]);
    float e[4], s = 0.f;
    for (int i = 0; i < m; i++) { e[i] = expf(l[i] - mx); s += e[i]; }
    float inv = 1.f / s;
    for (int i = 0; i < m; i++) sm[i] = e[i] * inv;
    int i1 = 0;
    for (int i = 1; i < m; i++) if (l[i] > l[i1]) i1 = i;
    int i2 = -1;
    for (int i = 0; i < m; i++) {
        if (i == i1) continue;
        if (i2 < 0 || l[i] > l[i2]) i2 = i;
    }
    float m2 = fmaxf(l[i1], l[i2]);
    float ea = expf(l[i1] - m2), eb = expf(l[i2] - m2);
    float si = 1.f / (ea + eb);
    g[i1] = ea * si; g[i2] = eb * si;
    oh[i1] = 1.f; oh[i2] = 1.f;
}

__global__ void routing_kernel(const float* __restrict__ logits, float* __restrict__ gdev,
                               float* __restrict__ og, float* __restrict__ ooh,
                               float* __restrict__ osm)
{
    int b = blockIdx.x * blockDim.x + threadIdx.x;
    if (b >= BATCH) return;
    float l[GOUT];
#pragma unroll
    for (int i = 0; i < GOUT; i++) l[i] = logits[b * GOUT + i];
    float g[GOUT], oh[GOUT], sm[GOUT];
#pragma unroll
    for (int i = 0; i < GOUT; i++) { g[i] = 0.f; oh[i] = 0.f; sm[i] = 0.f; }
    g[0] = 1.f; oh[0] = 1.f; sm[0] = 1.f;
    route_m(l + 1, 2, g + 1, oh + 1, sm + 1);
    route_m(l + 3, 3, g + 3, oh + 3, sm + 3);
    route_m(l + 6, 4, g + 6, oh + 6, sm + 6);
#pragma unroll
    for (int i = 0; i < GOUT; i++) {
        gdev[b * GOUT + i] = g[i];
        og  [b * GOUT + i] = g[i];
        ooh [b * GOUT + i] = oh[i];
        osm [b * GOUT + i] = sm[i];
    }
}

// dst[b,:] = sum_t gates[b, goff+t] * o_t[b,:]
__global__ void wsum_kernel(const float* __restrict__ gates, int goff, int nt,
                            const float* __restrict__ o0, const float* __restrict__ o1,
                            const float* __restrict__ o2, const float* __restrict__ o3,
                            float* __restrict__ dst)
{
    int idx = blockIdx.x * blockDim.x + threadIdx.x;
    if (idx >= BATCH * (HDIM / 4)) return;
    int b = idx / (HDIM / 4);
    const float* g = gates + b * GOUT + goff;
    float4 r = make_float4(0.f, 0.f, 0.f, 0.f);
    float w; float4 v;
    w = g[0]; v = ((const float4*)o0)[idx];
    r.x += w * v.x; r.y += w * v.y; r.z += w * v.z; r.w += w * v.w;
    if (nt > 1) {
        w = g[1]; v = ((const float4*)o1)[idx];
        r.x += w * v.x; r.y += w * v.y; r.z += w * v.z; r.w += w * v.w;
    }
    if (nt > 2) {
        w = g[2]; v = ((const float4*)o2)[idx];
        r.x += w * v.x; r.y += w * v.y; r.z += w * v.z; r.w += w * v.w;
    }
    if (nt > 3) {
        w = g[3]; v = ((const float4*)o3)[idx];
        r.x += w * v.x; r.y += w * v.y; r.z += w * v.z; r.w += w * v.w;
    }
    ((float4*)dst)[idx] = r;
}

// final = last_buf @ last_W + last_b   (N=18)
__global__ void final_kernel(const float* __restrict__ last, const float* __restrict__ W,
                             const float* __restrict__ b, float* __restrict__ out)
{
    int idx = blockIdx.x * blockDim.x + threadIdx.x;
    if (idx >= BATCH * OUTD) return;
    int row = idx / OUTD, o = idx % OUTD;
    const float4* lp = (const float4*)(last + row * HDIM);
    float s = 0.f;
    for (int k = 0; k < HDIM / 4; k++) {
        float4 v = lp[k];
        s += v.x * W[(4 * k + 0) * OUTD + o];
        s += v.y * W[(4 * k + 1) * OUTD + o];
        s += v.z * W[(4 * k + 2) * OUTD + o];
        s += v.w * W[(4 * k + 3) * OUTD + o];
    }
    out[idx] = s + b[o];
}

extern "C" void kernel_launch(void* const* d_in, const int* in_sizes, int n_in,
                              void* d_out, int out_size)
{
    const float* x        = (const float*)d_in[0];
    const float* em       = (const float*)d_in[1];
    const float* base_W0  = (const float*)d_in[2];
    const float* base_b0  = (const float*)d_in[3];
    const float* base_W1  = (const float*)d_in[4];
    const float* base_b1  = (const float*)d_in[5];
    const float* em_W0    = (const float*)d_in[6];
    const float* em_b0    = (const float*)d_in[7];
    const float* em_W1    = (const float*)d_in[8];
    const float* em_b1    = (const float*)d_in[9];
    const float* gate_W0  = (const float*)d_in[10];
    const float* gate_b0  = (const float*)d_in[11];
    const float* gate_W1  = (const float*)d_in[12];
    const float* gate_b1  = (const float*)d_in[13];
    const float* fc_W     = (const float*)d_in[14];
    const float* fc_b     = (const float*)d_in[15];
    const float* last_W   = (const float*)d_in[16];
    const float* last_b   = (const float*)d_in[17];
    float* out = (float*)d_out;

    float *h0, *base, *eh, *gin, *gh, *logits, *gates;
    float *o0, *o1, *o2, *o3, *inp, *last;
    __nv_bfloat16 *wbh, *wbl;
    cudaGetSymbolAddress((void**)&h0,   g_h0);
    cudaGetSymbolAddress((void**)&base, g_base);
    cudaGetSymbolAddress((void**)&eh,   g_eh);
    cudaGetSymbolAddress((void**)&gin,  g_gin);
    cudaGetSymbolAddress((void**)&gh,   g_gh);
    cudaGetSymbolAddress((void**)&logits, g_logits);
    cudaGetSymbolAddress((void**)&gates,  g_gates);
    cudaGetSymbolAddress((void**)&o0,  g_out0);
    cudaGetSymbolAddress((void**)&o1,  g_out1);
    cudaGetSymbolAddress((void**)&o2,  g_out2);
    cudaGetSymbolAddress((void**)&o3,  g_out3);
    cudaGetSymbolAddress((void**)&inp, g_inp);
    cudaGetSymbolAddress((void**)&last, g_last);
    cudaGetSymbolAddress((void**)&wbh,  g_wbh);
    cudaGetSymbolAddress((void**)&wbl,  g_wbl);

    const int OFF_G  = BATCH * OUTD;
    const int OFF_OH = OFF_G + BATCH * GOUT;
    const int OFF_SM = OFF_OH + BATCH * GOUT;

    const dim3 gridH (HDIM / 128, BATCH / 128);   // N=1024
    const dim3 gridGH(GH   / 128, BATCH / 128);   // N=512
    const dim3 gridTC(HDIM / 128, BATCH / 128);

    // 0) transpose + bf16-split fc weights
    transpose_split_kernel<<<dim3(32, 32, 4), dim3(32, 8)>>>(fc_W, wbh, wbl);

    // gating path, fp32 scalar (precision-critical)
    sgemm_kernel<false, true,  false><<<gridH, 256>>>(x, base_W0, base_b0, nullptr, h0, BATCH, HDIM, 64);
    sgemm_kernel<false, false, false><<<gridH, 256>>>(h0, base_W1, base_b1, nullptr, base, BATCH, HDIM, HDIM);
    ehidden_kernel<<<(BATCH * EMH + 255) / 256, 256>>>(em, em_W0, em_b0, eh);
    sgemm_kernel<false, true,  true ><<<gridH, 256>>>(eh, em_W1, em_b1, base, gin, BATCH, HDIM, EMH);
    sgemm_kernel<false, true,  false><<<gridGH, 256>>>(gin, gate_W0, gate_b0, nullptr, gh, BATCH, GH, HDIM);
    logits_kernel<<<(BATCH * 32 + 255) / 256, 256>>>(gh, gate_W1, gate_b1, logits);
    routing_kernel<<<(BATCH + 255) / 256, 256>>>(logits, gates, out + OFF_G, out + OFF_OH, out + OFF_SM);

    // fc chain on tensor cores (bf16x3, ~fp32 accurate; feeds only 'final')
    tc_gemm_kernel<true ><<<gridTC, 256>>>(base, wbh + 0ull * HDIM * HDIM, wbl + 0ull * HDIM * HDIM, fc_b + 0 * HDIM, o0);
    tc_gemm_kernel<false><<<gridTC, 256>>>(o0,   wbh + 1ull * HDIM * HDIM, wbl + 1ull * HDIM * HDIM, fc_b + 1 * HDIM, o1);
    wsum_kernel<<<(BATCH * HDIM / 4 + 255) / 256, 256>>>(gates, 1, 2, o0, o1, nullptr, nullptr, inp);
    tc_gemm_kernel<false><<<gridTC, 256>>>(inp,  wbh + 2ull * HDIM * HDIM, wbl + 2ull * HDIM * HDIM, fc_b + 2 * HDIM, o2);
    wsum_kernel<<<(BATCH * HDIM / 4 + 255) / 256, 256>>>(gates, 3, 3, o0, o1, o2, nullptr, inp);
    tc_gemm_kernel<false><<<gridTC, 256>>>(inp,  wbh + 3ull * HDIM * HDIM, wbl + 3ull * HDIM * HDIM, fc_b + 3 * HDIM, o3);
    wsum_kernel<<<(BATCH * HDIM / 4 + 255) / 256, 256>>>(gates, 6, 4, o0, o1, o2, o3, last);
    final_kernel<<<(BATCH * OUTD + 255) / 256, 256>>>(last, last_W, last_b, out);
}

// round 6
// speedup vs baseline: 1.9725x; 1.2410x over previous
#include <cuda_runtime.h>
#include <cuda_bf16.h>
#include <math.h>
#include <stdint.h>

#define BATCH 8192
#define HDIM  1024
#define GH    512
#define EMH   256
#define OUTD  18
#define GOUT  10

typedef unsigned long long u64;

// -------- scratch (device globals: allocation-free) --------
__device__ float g_h0  [BATCH*HDIM];
__device__ float g_base[BATCH*HDIM];
__device__ float g_eh  [BATCH*EMH];
__device__ float g_gin [BATCH*HDIM];
__device__ float g_gh  [BATCH*GH];
__device__ float g_logits[BATCH*GOUT];
__device__ float g_gates [BATCH*GOUT];
__device__ float g_out0[BATCH*HDIM];
__device__ float g_out1[BATCH*HDIM];
__device__ float g_out2[BATCH*HDIM];
__device__ float g_out3[BATCH*HDIM];
__device__ float g_inp [BATCH*HDIM];
__device__ float g_last[BATCH*HDIM];
__device__ __nv_bfloat16 g_wbh[4*HDIM*HDIM];     // fc weights [mod][N][K] hi
__device__ __nv_bfloat16 g_wbl[4*HDIM*HDIM];     // fc weights [mod][N][K] lo
__device__ __nv_bfloat16 g_gwh[2*HDIM*HDIM];     // gating weights (transposed, hi)
__device__ __nv_bfloat16 g_gwl[2*HDIM*HDIM];     // gating weights (transposed, lo)

// offsets inside g_gw*: base_W0t[1024][64], base_W1t[1024][1024],
//                       em_W1t[1024][256], gate_W0t[512][1024]
#define OFF_B0T 0
#define OFF_B1T (OFF_B0T + 1024*64)
#define OFF_EMT (OFF_B1T + 1024*1024)
#define OFF_G0T (OFF_EMT + 1024*256)

__device__ __forceinline__ void relu4(float4 &v) {
    v.x = fmaxf(v.x, 0.f); v.y = fmaxf(v.y, 0.f);
    v.z = fmaxf(v.z, 0.f); v.w = fmaxf(v.w, 0.f);
}

// =====================================================================
// bf16x3 split tensor-core GEMM (mma.sync.m16n8k16, baseline PTX):
//   C = epi( op(A) @ Wt^T + bias ),  A fp32 [M,K], Wt bf16 hi/lo [N][K]
//   epi: optional relu, optional elementwise mul by Cmul
// Error ~2^-18 per product (Ah*Bh + Ah*Bl + Al*Bh; Al*Bl dropped).
// CTA 128x128, K-slab 32, 8 warps (4 M x 2 N), warp tile 32x64.
// Requires M%128==0, N%128==0, K%32==0.
// =====================================================================
#define TCK 32
#define STR 40   // smem row stride in bf16 elems (conflict-free for frag map)

__device__ __forceinline__ void mma16816(float c[4], const uint32_t a[4],
                                         const uint32_t b[2]) {
    asm("mma.sync.aligned.m16n8k16.row.col.f32.bf16.bf16.f32 "
        "{%0,%1,%2,%3}, {%4,%5,%6,%7}, {%8,%9}, {%0,%1,%2,%3};"
        : "+f"(c[0]), "+f"(c[1]), "+f"(c[2]), "+f"(c[3])
        : "r"(a[0]), "r"(a[1]), "r"(a[2]), "r"(a[3]), "r"(b[0]), "r"(b[1]));
}

template<bool RELU_A, bool RELU_C, bool MUL_C>
__global__ __launch_bounds__(256, 2)
void tc_gemm_kernel(const float* __restrict__ A,
                    const __nv_bfloat16* __restrict__ Wh,
                    const __nv_bfloat16* __restrict__ Wl,
                    const float* __restrict__ bias,
                    const float* __restrict__ Cmul,
                    float* __restrict__ C, int N, int K)
{
    __shared__ uint16_t sAh[128 * STR];
    __shared__ uint16_t sAl[128 * STR];
    __shared__ uint16_t sBh[128 * STR];
    __shared__ uint16_t sBl[128 * STR];

    const int tid  = threadIdx.x;
    const int wid  = tid >> 5;
    const int lane = tid & 31;
    const int g = lane >> 2;         // 0..7
    const int t = lane & 3;          // 0..3
    const int warp_m = wid & 3;      // 0..3 -> 32-row band
    const int warp_n = wid >> 2;     // 0..1 -> 64-col band
    const int bm = blockIdx.y * 128;
    const int bn = blockIdx.x * 128;

    // staging map: 2 threads per row, 16 elems each
    const int srow = tid >> 1;
    const int kh   = (tid & 1) * 16;

    float acc[2][8][4];
#pragma unroll
    for (int mt = 0; mt < 2; mt++)
#pragma unroll
        for (int nt = 0; nt < 8; nt++)
#pragma unroll
            for (int e = 0; e < 4; e++) acc[mt][nt][e] = 0.f;

    const float* Ap = A + (u64)(bm + srow) * K + kh;
    const __nv_bfloat16* Bhp = Wh + (u64)(bn + srow) * K + kh;
    const __nv_bfloat16* Blp = Wl + (u64)(bn + srow) * K + kh;
    const int sbase = srow * STR + kh;

    for (int s = 0; s < K / TCK; s++) {
        // ---- stage A (fp32 -> bf16 hi/lo) ----
        float4 f[4];
#pragma unroll
        for (int i = 0; i < 4; i++) {
            f[i] = *(const float4*)(Ap + s * TCK + 4 * i);
            if (RELU_A) relu4(f[i]);
        }
        const float* fe = (const float*)f;
#pragma unroll
        for (int i = 0; i < 8; i++) {
            float v0 = fe[2 * i], v1 = fe[2 * i + 1];
            __nv_bfloat16 h0 = __float2bfloat16(v0);
            __nv_bfloat16 h1 = __float2bfloat16(v1);
            __nv_bfloat16 l0 = __float2bfloat16(v0 - __bfloat162float(h0));
            __nv_bfloat16 l1 = __float2bfloat16(v1 - __bfloat162float(h1));
            uint32_t ph = (uint32_t)__bfloat16_as_ushort(h0)
                        | ((uint32_t)__bfloat16_as_ushort(h1) << 16);
            uint32_t pl = (uint32_t)__bfloat16_as_ushort(l0)
                        | ((uint32_t)__bfloat16_as_ushort(l1) << 16);
            *(uint32_t*)&sAh[sbase + 2 * i] = ph;
            *(uint32_t*)&sAl[sbase + 2 * i] = pl;
        }
        // ---- stage B (bf16 direct copy) ----
        {
            const uint4* bh4 = (const uint4*)(Bhp + s * TCK);
            const uint4* bl4 = (const uint4*)(Blp + s * TCK);
            uint4 u0 = bh4[0], u1 = bh4[1];
            uint4 v0 = bl4[0], v1 = bl4[1];
            uint32_t* dh = (uint32_t*)&sBh[sbase];
            uint32_t* dl = (uint32_t*)&sBl[sbase];
            dh[0] = u0.x; dh[1] = u0.y; dh[2] = u0.z; dh[3] = u0.w;
            dh[4] = u1.x; dh[5] = u1.y; dh[6] = u1.z; dh[7] = u1.w;
            dl[0] = v0.x; dl[1] = v0.y; dl[2] = v0.z; dl[3] = v0.w;
            dl[4] = v1.x; dl[5] = v1.y; dl[6] = v1.z; dl[7] = v1.w;
        }
        __syncthreads();

        // ---- compute: 2 k16 steps ----
#pragma unroll
        for (int kk = 0; kk < TCK; kk += 16) {
            uint32_t ah[2][4], al[2][4];
#pragma unroll
            for (int mt = 0; mt < 2; mt++) {
                const int r0 = (warp_m * 32 + mt * 16 + g) * STR + kk + t * 2;
                const int r1 = r0 + 8 * STR;
                ah[mt][0] = *(const uint32_t*)&sAh[r0];
                ah[mt][1] = *(const uint32_t*)&sAh[r1];
                ah[mt][2] = *(const uint32_t*)&sAh[r0 + 8];
                ah[mt][3] = *(const uint32_t*)&sAh[r1 + 8];
                al[mt][0] = *(const uint32_t*)&sAl[r0];
                al[mt][1] = *(const uint32_t*)&sAl[r1];
                al[mt][2] = *(const uint32_t*)&sAl[r0 + 8];
                al[mt][3] = *(const uint32_t*)&sAl[r1 + 8];
            }
#pragma unroll
            for (int nt = 0; nt < 8; nt++) {
                const int nb = (warp_n * 64 + nt * 8 + g) * STR + kk + t * 2;
                uint32_t bh[2], bl[2];
                bh[0] = *(const uint32_t*)&sBh[nb];
                bh[1] = *(const uint32_t*)&sBh[nb + 8];
                bl[0] = *(const uint32_t*)&sBl[nb];
                bl[1] = *(const uint32_t*)&sBl[nb + 8];
#pragma unroll
                for (int mt = 0; mt < 2; mt++) {
                    mma16816(acc[mt][nt], ah[mt], bh);
                    mma16816(acc[mt][nt], ah[mt], bl);
                    mma16816(acc[mt][nt], al[mt], bh);
                }
            }
        }
        __syncthreads();
    }

    // ---- epilogue ----
#pragma unroll
    for (int mt = 0; mt < 2; mt++) {
#pragma unroll
        for (int nt = 0; nt < 8; nt++) {
            const int row = bm + warp_m * 32 + mt * 16 + g;
            const int col = bn + warp_n * 64 + nt * 8 + t * 2;
            const float b0 = bias[col], b1 = bias[col + 1];
            float2 v0, v1;
            v0.x = acc[mt][nt][0] + b0;
            v0.y = acc[mt][nt][1] + b1;
            v1.x = acc[mt][nt][2] + b0;
            v1.y = acc[mt][nt][3] + b1;
            if (RELU_C) {
                v0.x = fmaxf(v0.x, 0.f); v0.y = fmaxf(v0.y, 0.f);
                v1.x = fmaxf(v1.x, 0.f); v1.y = fmaxf(v1.y, 0.f);
            }
            if (MUL_C) {
                float2 m0 = *(const float2*)(Cmul + (u64)row * N + col);
                float2 m1 = *(const float2*)(Cmul + (u64)(row + 8) * N + col);
                v0.x *= m0.x; v0.y *= m0.y;
                v1.x *= m1.x; v1.y *= m1.y;
            }
            *(float2*)(C + (u64)row * N + col)       = v0;
            *(float2*)(C + (u64)(row + 8) * N + col) = v1;
        }
    }
}

// transpose + bf16-split: W [K,N] fp32 -> Wh/Wl [N,K] bf16 (K,N mult of 32)
__global__ void tsplit_kernel(const float* __restrict__ W,
                              __nv_bfloat16* __restrict__ Wh,
                              __nv_bfloat16* __restrict__ Wl, int K, int N)
{
    __shared__ float tile[32][33];
    const int k0 = blockIdx.y * 32, n0 = blockIdx.x * 32;
    const int tx = threadIdx.x, ty = threadIdx.y;
#pragma unroll
    for (int i = 0; i < 32; i += 8)
        tile[ty + i][tx] = W[(u64)(k0 + ty + i) * N + n0 + tx];
    __syncthreads();
#pragma unroll
    for (int i = 0; i < 32; i += 8) {
        float v = tile[tx][ty + i];
        __nv_bfloat16 h = __float2bfloat16(v);
        __nv_bfloat16 l = __float2bfloat16(v - __bfloat162float(h));
        Wh[(u64)(n0 + ty + i) * K + k0 + tx] = h;
        Wl[(u64)(n0 + ty + i) * K + k0 + tx] = l;
    }
}

// em hidden: eh[b,j] = relu(em[b]*em_W0[j] + em_b0[j])
__global__ void ehidden_kernel(const float* __restrict__ em, const float* __restrict__ W0,
                               const float* __restrict__ b0, float* __restrict__ eh)
{
    int idx = blockIdx.x * blockDim.x + threadIdx.x;
    if (idx >= BATCH * EMH) return;
    int b = idx >> 8;
    int j = idx & (EMH - 1);
    eh[idx] = fmaxf(em[b] * W0[j] + b0[j], 0.f);
}

// logits = gate_h @ gate_W1 + gate_b1  (warp-per-row, shuffle reduce, fp32)
__global__ void logits_kernel(const float* __restrict__ gh, const float* __restrict__ W,
                              const float* __restrict__ b, float* __restrict__ logits)
{
    int warp = (blockIdx.x * blockDim.x + threadIdx.x) >> 5;
    int lane = threadIdx.x & 31;
    if (warp >= BATCH) return;
    const float* g = gh + warp * GH;
    float acc[GOUT];
#pragma unroll
    for (int j = 0; j < GOUT; j++) acc[j] = 0.f;
    for (int k = lane; k < GH; k += 32) {
        float gv = g[k];
        const float* wr = W + k * GOUT;
#pragma unroll
        for (int j = 0; j < GOUT; j++) acc[j] += gv * wr[j];
    }
#pragma unroll
    for (int j = 0; j < GOUT; j++) {
#pragma unroll
        for (int o = 16; o > 0; o >>= 1)
            acc[j] += __shfl_xor_sync(0xffffffffu, acc[j], o);
    }
    if (lane == 0) {
        float* dst = logits + warp * GOUT;
#pragma unroll
        for (int j = 0; j < GOUT; j++) dst[j] = acc[j] + b[j];
    }
}

// Routing: top-2 + softmax gates per module group (matches jax.lax.top_k ties)
__device__ __forceinline__ void route_m(const float* l, int m,
                                        float* g, float* oh, float* sm)
{
    float mx = l[0];
    for (int i = 1; i < m; i++) mx = fmaxf(mx, l[i]);
    float e[4], s = 0.f;
    for (int i = 0; i < m; i++) { e[i] = expf(l[i] - mx); s += e[i]; }
    float inv = 1.f / s;
    for (int i = 0; i < m; i++) sm[i] = e[i] * inv;
    int i1 = 0;
    for (int i = 1; i < m; i++) if (l[i] > l[i1]) i1 = i;
    int i2 = -1;
    for (int i = 0; i < m; i++) {
        if (i == i1) continue;
        if (i2 < 0 || l[i] > l[i2]) i2 = i;
    }
    float m2 = fmaxf(l[i1], l[i2]);
    float ea = expf(l[i1] - m2), eb = expf(l[i2] - m2);
    float si = 1.f / (ea + eb);
    g[i1] = ea * si; g[i2] = eb * si;
    oh[i1] = 1.f; oh[i2] = 1.f;
}

__global__ void routing_kernel(const float* __restrict__ logits, float* __restrict__ gdev,
                               float* __restrict__ og, float* __restrict__ ooh,
                               float* __restrict__ osm)
{
    int b = blockIdx.x * blockDim.x + threadIdx.x;
    if (b >= BATCH) return;
    float l[GOUT];
#pragma unroll
    for (int i = 0; i < GOUT; i++) l[i] = logits[b * GOUT + i];
    float g[GOUT], oh[GOUT], sm[GOUT];
#pragma unroll
    for (int i = 0; i < GOUT; i++) { g[i] = 0.f; oh[i] = 0.f; sm[i] = 0.f; }
    g[0] = 1.f; oh[0] = 1.f; sm[0] = 1.f;
    route_m(l + 1, 2, g + 1, oh + 1, sm + 1);
    route_m(l + 3, 3, g + 3, oh + 3, sm + 3);
    route_m(l + 6, 4, g + 6, oh + 6, sm + 6);
#pragma unroll
    for (int i = 0; i < GOUT; i++) {
        gdev[b * GOUT + i] = g[i];
        og  [b * GOUT + i] = g[i];
        ooh [b * GOUT + i] = oh[i];
        osm [b * GOUT + i] = sm[i];
    }
}

// dst[b,:] = sum_t gates[b, goff+t] * o_t[b,:]
__global__ void wsum_kernel(const float* __restrict__ gates, int goff, int nt,
                            const float* __restrict__ o0, const float* __restrict__ o1,
                            const float* __restrict__ o2, const float* __restrict__ o3,
                            float* __restrict__ dst)
{
    int idx = blockIdx.x * blockDim.x + threadIdx.x;
    if (idx >= BATCH * (HDIM / 4)) return;
    int b = idx / (HDIM / 4);
    const float* g = gates + b * GOUT + goff;
    float4 r = make_float4(0.f, 0.f, 0.f, 0.f);
    float w; float4 v;
    w = g[0]; v = ((const float4*)o0)[idx];
    r.x += w * v.x; r.y += w * v.y; r.z += w * v.z; r.w += w * v.w;
    if (nt > 1) {
        w = g[1]; v = ((const float4*)o1)[idx];
        r.x += w * v.x; r.y += w * v.y; r.z += w * v.z; r.w += w * v.w;
    }
    if (nt > 2) {
        w = g[2]; v = ((const float4*)o2)[idx];
        r.x += w * v.x; r.y += w * v.y; r.z += w * v.z; r.w += w * v.w;
    }
    if (nt > 3) {
        w = g[3]; v = ((const float4*)o3)[idx];
        r.x += w * v.x; r.y += w * v.y; r.z += w * v.z; r.w += w * v.w;
    }
    ((float4*)dst)[idx] = r;
}

// final = last_buf @ last_W + last_b   (N=18)
__global__ void final_kernel(const float* __restrict__ last, const float* __restrict__ W,
                             const float* __restrict__ b, float* __restrict__ out)
{
    int idx = blockIdx.x * blockDim.x + threadIdx.x;
    if (idx >= BATCH * OUTD) return;
    int row = idx / OUTD, o = idx % OUTD;
    const float4* lp = (const float4*)(last + row * HDIM);
    float s = 0.f;
    for (int k = 0; k < HDIM / 4; k++) {
        float4 v = lp[k];
        s += v.x * W[(4 * k + 0) * OUTD + o];
        s += v.y * W[(4 * k + 1) * OUTD + o];
        s += v.z * W[(4 * k + 2) * OUTD + o];
        s += v.w * W[(4 * k + 3) * OUTD + o];
    }
    out[idx] = s + b[o];
}

extern "C" void kernel_launch(void* const* d_in, const int* in_sizes, int n_in,
                              void* d_out, int out_size)
{
    const float* x        = (const float*)d_in[0];
    const float* em       = (const float*)d_in[1];
    const float* base_W0  = (const float*)d_in[2];
    const float* base_b0  = (const float*)d_in[3];
    const float* base_W1  = (const float*)d_in[4];
    const float* base_b1  = (const float*)d_in[5];
    const float* em_W0    = (const float*)d_in[6];
    const float* em_b0    = (const float*)d_in[7];
    const float* em_W1    = (const float*)d_in[8];
    const float* em_b1    = (const float*)d_in[9];
    const float* gate_W0  = (const float*)d_in[10];
    const float* gate_b0  = (const float*)d_in[11];
    const float* gate_W1  = (const float*)d_in[12];
    const float* gate_b1  = (const float*)d_in[13];
    const float* fc_W     = (const float*)d_in[14];
    const float* fc_b     = (const float*)d_in[15];
    const float* last_W   = (const float*)d_in[16];
    const float* last_b   = (const float*)d_in[17];
    float* out = (float*)d_out;

    float *h0, *base, *eh, *gin, *gh, *logits, *gates;
    float *o0, *o1, *o2, *o3, *inp, *last;
    __nv_bfloat16 *wbh, *wbl, *gwh, *gwl;
    cudaGetSymbolAddress((void**)&h0,   g_h0);
    cudaGetSymbolAddress((void**)&base, g_base);
    cudaGetSymbolAddress((void**)&eh,   g_eh);
    cudaGetSymbolAddress((void**)&gin,  g_gin);
    cudaGetSymbolAddress((void**)&gh,   g_gh);
    cudaGetSymbolAddress((void**)&logits, g_logits);
    cudaGetSymbolAddress((void**)&gates,  g_gates);
    cudaGetSymbolAddress((void**)&o0,  g_out0);
    cudaGetSymbolAddress((void**)&o1,  g_out1);
    cudaGetSymbolAddress((void**)&o2,  g_out2);
    cudaGetSymbolAddress((void**)&o3,  g_out3);
    cudaGetSymbolAddress((void**)&inp, g_inp);
    cudaGetSymbolAddress((void**)&last, g_last);
    cudaGetSymbolAddress((void**)&wbh,  g_wbh);
    cudaGetSymbolAddress((void**)&wbl,  g_wbl);
    cudaGetSymbolAddress((void**)&gwh,  g_gwh);
    cudaGetSymbolAddress((void**)&gwl,  g_gwl);

    const int OFF_G  = BATCH * OUTD;
    const int OFF_OH = OFF_G + BATCH * GOUT;
    const int OFF_SM = OFF_OH + BATCH * GOUT;

    const dim3 blkT(32, 8);
    const dim3 gridTC(HDIM / 128, BATCH / 128);   // N=1024 tiles
    const dim3 gridTG(GH   / 128, BATCH / 128);   // N=512 tiles

    // ---- weight prep: transpose + bf16 hi/lo split ----
    tsplit_kernel<<<dim3(32, 2),  blkT>>>(base_W0, gwh + OFF_B0T, gwl + OFF_B0T, 64,   HDIM);
    tsplit_kernel<<<dim3(32, 32), blkT>>>(base_W1, gwh + OFF_B1T, gwl + OFF_B1T, HDIM, HDIM);
    tsplit_kernel<<<dim3(32, 8),  blkT>>>(em_W1,   gwh + OFF_EMT, gwl + OFF_EMT, EMH,  HDIM);
    tsplit_kernel<<<dim3(16, 32), blkT>>>(gate_W0, gwh + OFF_G0T, gwl + OFF_G0T, HDIM, GH);
    for (int m = 0; m < 4; m++)
        tsplit_kernel<<<dim3(32, 32), blkT>>>(fc_W + (u64)m * HDIM * HDIM,
                                              wbh + (u64)m * HDIM * HDIM,
                                              wbl + (u64)m * HDIM * HDIM, HDIM, HDIM);

    // ---- gating path (bf16x3 tensor; abs logit error ~1e-7, flip-safe) ----
    // 1) h0 = relu(x @ base_W0 + b0)          [K=64]
    tc_gemm_kernel<false, true,  false><<<gridTC, 256>>>(x, gwh + OFF_B0T, gwl + OFF_B0T, base_b0, nullptr, h0, HDIM, 64);
    // 2) base_out = h0 @ base_W1 + b1         [K=1024, no relu]
    tc_gemm_kernel<false, false, false><<<gridTC, 256>>>(h0, gwh + OFF_B1T, gwl + OFF_B1T, base_b1, nullptr, base, HDIM, HDIM);
    // 3) eh = relu(em * em_W0 + em_b0)
    ehidden_kernel<<<(BATCH * EMH + 255) / 256, 256>>>(em, em_W0, em_b0, eh);
    // 4) gate_in = relu(eh @ em_W1 + em_b1) * base_out   [K=256]
    tc_gemm_kernel<false, true,  true ><<<gridTC, 256>>>(eh, gwh + OFF_EMT, gwl + OFF_EMT, em_b1, base, gin, HDIM, EMH);
    // 5) gate_h = relu(gate_in @ gate_W0 + gate_b0)      [N=512]
    tc_gemm_kernel<false, true,  false><<<gridTG, 256>>>(gin, gwh + OFF_G0T, gwl + OFF_G0T, gate_b0, nullptr, gh, GH, HDIM);
    // 6) logits (fp32)
    logits_kernel<<<(BATCH * 32 + 255) / 256, 256>>>(gh, gate_W1, gate_b1, logits);
    // 7) routing
    routing_kernel<<<(BATCH + 255) / 256, 256>>>(logits, gates, out + OFF_G, out + OFF_OH, out + OFF_SM);

    // ---- fc chain (bf16x3 tensor) ----
    tc_gemm_kernel<true,  true, false><<<gridTC, 256>>>(base, wbh + 0ull * HDIM * HDIM, wbl + 0ull * HDIM * HDIM, fc_b + 0 * HDIM, nullptr, o0, HDIM, HDIM);
    tc_gemm_kernel<false, true, false><<<gridTC, 256>>>(o0,   wbh + 1ull * HDIM * HDIM, wbl + 1ull * HDIM * HDIM, fc_b + 1 * HDIM, nullptr, o1, HDIM, HDIM);
    wsum_kernel<<<(BATCH * HDIM / 4 + 255) / 256, 256>>>(gates, 1, 2, o0, o1, nullptr, nullptr, inp);
    tc_gemm_kernel<false, true, false><<<gridTC, 256>>>(inp,  wbh + 2ull * HDIM * HDIM, wbl + 2ull * HDIM * HDIM, fc_b + 2 * HDIM, nullptr, o2, HDIM, HDIM);
    wsum_kernel<<<(BATCH * HDIM / 4 + 255) / 256, 256>>>(gates, 3, 3, o0, o1, o2, nullptr, inp);
    tc_gemm_kernel<false, true, false><<<gridTC, 256>>>(inp,  wbh + 3ull * HDIM * HDIM, wbl + 3ull * HDIM * HDIM, fc_b + 3 * HDIM, nullptr, o3, HDIM, HDIM);
    wsum_kernel<<<(BATCH * HDIM / 4 + 255) / 256, 256>>>(gates, 6, 4, o0, o1, o2, o3, last);
    final_kernel<<<(BATCH * OUTD + 255) / 256, 256>>>(last, last_W, last_b, out);
}

// round 7
// speedup vs baseline: 2.5648x; 1.3003x over previous
#include <cuda_runtime.h>
#include <cuda_bf16.h>
#include <math.h>
#include <stdint.h>

#define BATCH 8192
#define HDIM  1024
#define GH    512
#define EMH   256
#define OUTD  18
#define GOUT  10

typedef unsigned long long u64;

// -------- scratch (device globals: allocation-free) --------
__device__ float g_h0  [BATCH*HDIM];
__device__ float g_base[BATCH*HDIM];
__device__ float g_eh  [BATCH*EMH];
__device__ float g_gin [BATCH*HDIM];
__device__ float g_gh  [BATCH*GH];
__device__ float g_logits[BATCH*GOUT];
__device__ float g_gates [BATCH*GOUT];
__device__ float g_out0[BATCH*HDIM];
__device__ float g_out1[BATCH*HDIM];
__device__ float g_out2[BATCH*HDIM];
__device__ float g_out3[BATCH*HDIM];
__device__ float g_inp [BATCH*HDIM];
__device__ float g_last[BATCH*HDIM];
__device__ __nv_bfloat16 g_wbh[4*HDIM*HDIM];     // fc weights [mod][N][K] hi
__device__ __nv_bfloat16 g_wbl[4*HDIM*HDIM];     // fc weights [mod][N][K] lo
__device__ __nv_bfloat16 g_gwh[2*HDIM*HDIM];     // gating weights (transposed, hi)
__device__ __nv_bfloat16 g_gwl[2*HDIM*HDIM];     // gating weights (transposed, lo)

#define OFF_B0T 0
#define OFF_B1T (OFF_B0T + 1024*64)
#define OFF_EMT (OFF_B1T + 1024*1024)
#define OFF_G0T (OFF_EMT + 1024*256)

__device__ __forceinline__ void relu4(float4 &v) {
    v.x = fmaxf(v.x, 0.f); v.y = fmaxf(v.y, 0.f);
    v.z = fmaxf(v.z, 0.f); v.w = fmaxf(v.w, 0.f);
}

// =====================================================================
// bf16x3 split tensor-core GEMM, pipelined:
//   C = epi( op(A) @ Wt^T + bias ),  A fp32 [M,K], Wt bf16 hi/lo [N][K]
// CTA 128x128, K-slab 32, 8 warps (4Mx2N), warp tile 32x64.
// Double-buffered smem (cp.async for B, LDG+cvt+STS for A), ldmatrix frags.
// Requires M%128==0, N%128==0, K%32==0.
// =====================================================================
#define TCK 32
#define STR 40                      // smem row stride (bf16 elems)
#define ARR 5120                    // one array: 128*STR elems
#define BUFB 40960                  // one buffer: 4 arrays in bytes
#define SMEM_DYN (2*BUFB)           // 81920 bytes

#define CPASYNC16(dst, src) \
    asm volatile("cp.async.ca.shared.global [%0], [%1], 16;" :: "r"(dst), "l"(src))
#define CPCOMMIT() asm volatile("cp.async.commit_group;" ::: "memory")
#define CPWAIT0()  asm volatile("cp.async.wait_group 0;"  ::: "memory")
#define LDSM4(r0, r1, r2, r3, addr) \
    asm volatile("ldmatrix.sync.aligned.m8n8.x4.shared.b16 {%0,%1,%2,%3}, [%4];" \
                 : "=r"(r0), "=r"(r1), "=r"(r2), "=r"(r3) : "r"(addr))

__device__ __forceinline__ void mma16816(float c[4], const uint32_t a[4],
                                         uint32_t b0, uint32_t b1) {
    asm("mma.sync.aligned.m16n8k16.row.col.f32.bf16.bf16.f32 "
        "{%0,%1,%2,%3}, {%4,%5,%6,%7}, {%8,%9}, {%0,%1,%2,%3};"
        : "+f"(c[0]), "+f"(c[1]), "+f"(c[2]), "+f"(c[3])
        : "r"(a[0]), "r"(a[1]), "r"(a[2]), "r"(a[3]), "r"(b0), "r"(b1));
}

template<bool RELU_A, bool RELU_C, bool MUL_C>
__global__ __launch_bounds__(256, 2)
void tc_gemm_kernel(const float* __restrict__ A,
                    const __nv_bfloat16* __restrict__ Wh,
                    const __nv_bfloat16* __restrict__ Wl,
                    const float* __restrict__ bias,
                    const float* __restrict__ Cmul,
                    float* __restrict__ C, int N, int K)
{
    extern __shared__ uint16_t dsm[];
    const uint32_t smem_u = (uint32_t)__cvta_generic_to_shared(dsm);

    const int tid  = threadIdx.x;
    const int wid  = tid >> 5;
    const int lane = tid & 31;
    const int g = lane >> 2;
    const int t = lane & 3;
    const int warp_m = wid & 3;
    const int warp_n = wid >> 2;
    const int bm = blockIdx.y * 128;
    const int bn = blockIdx.x * 128;

    // staging map: 2 threads per row, 16 elems each
    const int srow = tid >> 1;
    const int kh   = (tid & 1) * 16;
    const uint32_t sbyte = (uint32_t)(srow * STR + kh) * 2;

    const float* Ap = A + (u64)(bm + srow) * K + kh;
    const __nv_bfloat16* Bhp = Wh + (u64)(bn + srow) * K + kh;
    const __nv_bfloat16* Blp = Wl + (u64)(bn + srow) * K + kh;

    // ldmatrix lane addresses (byte offsets within one array)
    uint32_t aOff[2], bOff[4];
#pragma unroll
    for (int mt = 0; mt < 2; mt++)
        aOff[mt] = (uint32_t)(((warp_m * 32 + mt * 16 + (lane & 15)) * STR
                              + ((lane >> 4) & 1) * 8) * 2);
#pragma unroll
    for (int np = 0; np < 4; np++)
        bOff[np] = (uint32_t)(((warp_n * 64 + np * 16 + ((lane >> 4) & 1) * 8 + (lane & 7)) * STR
                              + ((lane >> 3) & 1) * 8) * 2);

    float acc[2][8][4];
#pragma unroll
    for (int mt = 0; mt < 2; mt++)
#pragma unroll
        for (int nt = 0; nt < 8; nt++)
#pragma unroll
            for (int e = 0; e < 4; e++) acc[mt][nt][e] = 0.f;

    const int nslab = K / TCK;

    // ---- staging helpers ----
    auto stageB = [&](int s, int p) {
        const __nv_bfloat16* bh = Bhp + s * TCK;
        const __nv_bfloat16* bl = Blp + s * TCK;
        uint32_t dh = smem_u + p * BUFB + 2 * ARR * 2 + sbyte;   // Bh array
        uint32_t dl = smem_u + p * BUFB + 3 * ARR * 2 + sbyte;   // Bl array
        CPASYNC16(dh,      bh);
        CPASYNC16(dh + 16, bh + 8);
        CPASYNC16(dl,      bl);
        CPASYNC16(dl + 16, bl + 8);
    };
    auto stageA = [&](int s, int p) {
        float4 f[4];
#pragma unroll
        for (int i = 0; i < 4; i++) {
            f[i] = *(const float4*)(Ap + s * TCK + 4 * i);
            if (RELU_A) relu4(f[i]);
        }
        const float* fe = (const float*)f;
        uint32_t ph[8], pl[8];
#pragma unroll
        for (int i = 0; i < 8; i++) {
            float v0 = fe[2 * i], v1 = fe[2 * i + 1];
            __nv_bfloat16 h0 = __float2bfloat16(v0);
            __nv_bfloat16 h1 = __float2bfloat16(v1);
            __nv_bfloat16 l0 = __float2bfloat16(v0 - __bfloat162float(h0));
            __nv_bfloat16 l1 = __float2bfloat16(v1 - __bfloat162float(h1));
            ph[i] = (uint32_t)__bfloat16_as_ushort(h0)
                  | ((uint32_t)__bfloat16_as_ushort(h1) << 16);
            pl[i] = (uint32_t)__bfloat16_as_ushort(l0)
                  | ((uint32_t)__bfloat16_as_ushort(l1) << 16);
        }
        uint32_t dh = smem_u + p * BUFB + sbyte;                 // Ah array
        uint32_t dl = smem_u + p * BUFB + ARR * 2 + sbyte;       // Al array
        asm volatile("st.shared.v4.b32 [%0], {%1,%2,%3,%4};" ::
                     "r"(dh), "r"(ph[0]), "r"(ph[1]), "r"(ph[2]), "r"(ph[3]) : "memory");
        asm volatile("st.shared.v4.b32 [%0], {%1,%2,%3,%4};" ::
                     "r"(dh + 16), "r"(ph[4]), "r"(ph[5]), "r"(ph[6]), "r"(ph[7]) : "memory");
        asm volatile("st.shared.v4.b32 [%0], {%1,%2,%3,%4};" ::
                     "r"(dl), "r"(pl[0]), "r"(pl[1]), "r"(pl[2]), "r"(pl[3]) : "memory");
        asm volatile("st.shared.v4.b32 [%0], {%1,%2,%3,%4};" ::
                     "r"(dl + 16), "r"(pl[4]), "r"(pl[5]), "r"(pl[6]), "r"(pl[7]) : "memory");
    };

    // ---- prologue: stage slab 0 into buffer 0 ----
    stageB(0, 0);
    CPCOMMIT();
    stageA(0, 0);
    CPWAIT0();
    __syncthreads();

    for (int s = 0; s < nslab; s++) {
        const int p = s & 1;
        if (s + 1 < nslab) {
            stageB(s + 1, p ^ 1);
            CPCOMMIT();
            stageA(s + 1, p ^ 1);     // writes buffer p^1 (all readers passed barrier)
        }

        const uint32_t pb = smem_u + p * BUFB;
#pragma unroll
        for (int kk = 0; kk < 2; kk++) {
            const uint32_t ko = kk * 32;    // 16 elems = 32 bytes
            uint32_t ah[2][4], al[2][4];
            LDSM4(ah[0][0], ah[0][1], ah[0][2], ah[0][3], pb + aOff[0] + ko);
            LDSM4(ah[1][0], ah[1][1], ah[1][2], ah[1][3], pb + aOff[1] + ko);
            LDSM4(al[0][0], al[0][1], al[0][2], al[0][3], pb + 2 * ARR + aOff[0] + ko);
            LDSM4(al[1][0], al[1][1], al[1][2], al[1][3], pb + 2 * ARR + aOff[1] + ko);
#pragma unroll
            for (int np = 0; np < 4; np++) {
                uint32_t bh[4], bl[4];
                LDSM4(bh[0], bh[1], bh[2], bh[3], pb + 4 * ARR + bOff[np] + ko);
                LDSM4(bl[0], bl[1], bl[2], bl[3], pb + 6 * ARR + bOff[np] + ko);
#pragma unroll
                for (int mt = 0; mt < 2; mt++) {
                    mma16816(acc[mt][2 * np + 0], ah[mt], bh[0], bh[1]);
                    mma16816(acc[mt][2 * np + 0], ah[mt], bl[0], bl[1]);
                    mma16816(acc[mt][2 * np + 0], al[mt], bh[0], bh[1]);
                    mma16816(acc[mt][2 * np + 1], ah[mt], bh[2], bh[3]);
                    mma16816(acc[mt][2 * np + 1], ah[mt], bl[2], bl[3]);
                    mma16816(acc[mt][2 * np + 1], al[mt], bh[2], bh[3]);
                }
            }
        }
        CPWAIT0();
        __syncthreads();
    }

    // ---- epilogue ----
#pragma unroll
    for (int mt = 0; mt < 2; mt++) {
#pragma unroll
        for (int nt = 0; nt < 8; nt++) {
            const int row = bm + warp_m * 32 + mt * 16 + g;
            const int col = bn + warp_n * 64 + nt * 8 + t * 2;
            const float b0 = bias[col], b1 = bias[col + 1];
            float2 v0, v1;
            v0.x = acc[mt][nt][0] + b0;
            v0.y = acc[mt][nt][1] + b1;
            v1.x = acc[mt][nt][2] + b0;
            v1.y = acc[mt][nt][3] + b1;
            if (RELU_C) {
                v0.x = fmaxf(v0.x, 0.f); v0.y = fmaxf(v0.y, 0.f);
                v1.x = fmaxf(v1.x, 0.f); v1.y = fmaxf(v1.y, 0.f);
            }
            if (MUL_C) {
                float2 m0 = *(const float2*)(Cmul + (u64)row * N + col);
                float2 m1 = *(const float2*)(Cmul + (u64)(row + 8) * N + col);
                v0.x *= m0.x; v0.y *= m0.y;
                v1.x *= m1.x; v1.y *= m1.y;
            }
            *(float2*)(C + (u64)row * N + col)       = v0;
            *(float2*)(C + (u64)(row + 8) * N + col) = v1;
        }
    }
}

// transpose + bf16-split: W [K,N] fp32 -> Wh/Wl [N,K] bf16
__global__ void tsplit_kernel(const float* __restrict__ W,
                              __nv_bfloat16* __restrict__ Wh,
                              __nv_bfloat16* __restrict__ Wl, int K, int N)
{
    __shared__ float tile[32][33];
    const int k0 = blockIdx.y * 32, n0 = blockIdx.x * 32;
    const int tx = threadIdx.x, ty = threadIdx.y;
#pragma unroll
    for (int i = 0; i < 32; i += 8)
        tile[ty + i][tx] = W[(u64)(k0 + ty + i) * N + n0 + tx];
    __syncthreads();
#pragma unroll
    for (int i = 0; i < 32; i += 8) {
        float v = tile[tx][ty + i];
        __nv_bfloat16 h = __float2bfloat16(v);
        __nv_bfloat16 l = __float2bfloat16(v - __bfloat162float(h));
        Wh[(u64)(n0 + ty + i) * K + k0 + tx] = h;
        Wl[(u64)(n0 + ty + i) * K + k0 + tx] = l;
    }
}

// em hidden: eh[b,j] = relu(em[b]*em_W0[j] + em_b0[j])
__global__ void ehidden_kernel(const float* __restrict__ em, const float* __restrict__ W0,
                               const float* __restrict__ b0, float* __restrict__ eh)
{
    int idx = blockIdx.x * blockDim.x + threadIdx.x;
    if (idx >= BATCH * EMH) return;
    int b = idx >> 8;
    int j = idx & (EMH - 1);
    eh[idx] = fmaxf(em[b] * W0[j] + b0[j], 0.f);
}

// logits = gate_h @ gate_W1 + gate_b1  (warp-per-row, shuffle reduce, fp32)
__global__ void logits_kernel(const float* __restrict__ gh, const float* __restrict__ W,
                              const float* __restrict__ b, float* __restrict__ logits)
{
    int warp = (blockIdx.x * blockDim.x + threadIdx.x) >> 5;
    int lane = threadIdx.x & 31;
    if (warp >= BATCH) return;
    const float* g = gh + warp * GH;
    float acc[GOUT];
#pragma unroll
    for (int j = 0; j < GOUT; j++) acc[j] = 0.f;
    for (int k = lane; k < GH; k += 32) {
        float gv = g[k];
        const float* wr = W + k * GOUT;
#pragma unroll
        for (int j = 0; j < GOUT; j++) acc[j] += gv * wr[j];
    }
#pragma unroll
    for (int j = 0; j < GOUT; j++) {
#pragma unroll
        for (int o = 16; o > 0; o >>= 1)
            acc[j] += __shfl_xor_sync(0xffffffffu, acc[j], o);
    }
    if (lane == 0) {
        float* dst = logits + warp * GOUT;
#pragma unroll
        for (int j = 0; j < GOUT; j++) dst[j] = acc[j] + b[j];
    }
}

// Routing: top-2 + softmax gates per module group (matches jax.lax.top_k ties)
__device__ __forceinline__ void route_m(const float* l, int m,
                                        float* g, float* oh, float* sm)
{
    float mx = l[0];
    for (int i = 1; i < m; i++) mx = fmaxf(mx, l[i]);
    float e[4], s = 0.f;
    for (int i = 0; i < m; i++) { e[i] = expf(l[i] - mx); s += e[i]; }
    float inv = 1.f / s;
    for (int i = 0; i < m; i++) sm[i] = e[i] * inv;
    int i1 = 0;
    for (int i = 1; i < m; i++) if (l[i] > l[i1]) i1 = i;
    int i2 = -1;
    for (int i = 0; i < m; i++) {
        if (i == i1) continue;
        if (i2 < 0 || l[i] > l[i2]) i2 = i;
    }
    float m2 = fmaxf(l[i1], l[i2]);
    float ea = expf(l[i1] - m2), eb = expf(l[i2] - m2);
    float si = 1.f / (ea + eb);
    g[i1] = ea * si; g[i2] = eb * si;
    oh[i1] = 1.f; oh[i2] = 1.f;
}

__global__ void routing_kernel(const float* __restrict__ logits, float* __restrict__ gdev,
                               float* __restrict__ og, float* __restrict__ ooh,
                               float* __restrict__ osm)
{
    int b = blockIdx.x * blockDim.x + threadIdx.x;
    if (b >= BATCH) return;
    float l[GOUT];
#pragma unroll
    for (int i = 0; i < GOUT; i++) l[i] = logits[b * GOUT + i];
    float g[GOUT], oh[GOUT], sm[GOUT];
#pragma unroll
    for (int i = 0; i < GOUT; i++) { g[i] = 0.f; oh[i] = 0.f; sm[i] = 0.f; }
    g[0] = 1.f; oh[0] = 1.f; sm[0] = 1.f;
    route_m(l + 1, 2, g + 1, oh + 1, sm + 1);
    route_m(l + 3, 3, g + 3, oh + 3, sm + 3);
    route_m(l + 6, 4, g + 6, oh + 6, sm + 6);
#pragma unroll
    for (int i = 0; i < GOUT; i++) {
        gdev[b * GOUT + i] = g[i];
        og  [b * GOUT + i] = g[i];
        ooh [b * GOUT + i] = oh[i];
        osm [b * GOUT + i] = sm[i];
    }
}

// dst[b,:] = sum_t gates[b, goff+t] * o_t[b,:]
__global__ void wsum_kernel(const float* __restrict__ gates, int goff, int nt,
                            const float* __restrict__ o0, const float* __restrict__ o1,
                            const float* __restrict__ o2, const float* __restrict__ o3,
                            float* __restrict__ dst)
{
    int idx = blockIdx.x * blockDim.x + threadIdx.x;
    if (idx >= BATCH * (HDIM / 4)) return;
    int b = idx / (HDIM / 4);
    const float* g = gates + b * GOUT + goff;
    float4 r = make_float4(0.f, 0.f, 0.f, 0.f);
    float w; float4 v;
    w = g[0]; v = ((const float4*)o0)[idx];
    r.x += w * v.x; r.y += w * v.y; r.z += w * v.z; r.w += w * v.w;
    if (nt > 1) {
        w = g[1]; v = ((const float4*)o1)[idx];
        r.x += w * v.x; r.y += w * v.y; r.z += w * v.z; r.w += w * v.w;
    }
    if (nt > 2) {
        w = g[2]; v = ((const float4*)o2)[idx];
        r.x += w * v.x; r.y += w * v.y; r.z += w * v.z; r.w += w * v.w;
    }
    if (nt > 3) {
        w = g[3]; v = ((const float4*)o3)[idx];
        r.x += w * v.x; r.y += w * v.y; r.z += w * v.z; r.w += w * v.w;
    }
    ((float4*)dst)[idx] = r;
}

// final = last_buf @ last_W + last_b   (N=18)
__global__ void final_kernel(const float* __restrict__ last, const float* __restrict__ W,
                             const float* __restrict__ b, float* __restrict__ out)
{
    int idx = blockIdx.x * blockDim.x + threadIdx.x;
    if (idx >= BATCH * OUTD) return;
    int row = idx / OUTD, o = idx % OUTD;
    const float4* lp = (const float4*)(last + row * HDIM);
    float s = 0.f;
    for (int k = 0; k < HDIM / 4; k++) {
        float4 v = lp[k];
        s += v.x * W[(4 * k + 0) * OUTD + o];
        s += v.y * W[(4 * k + 1) * OUTD + o];
        s += v.z * W[(4 * k + 2) * OUTD + o];
        s += v.w * W[(4 * k + 3) * OUTD + o];
    }
    out[idx] = s + b[o];
}

extern "C" void kernel_launch(void* const* d_in, const int* in_sizes, int n_in,
                              void* d_out, int out_size)
{
    const float* x        = (const float*)d_in[0];
    const float* em       = (const float*)d_in[1];
    const float* base_W0  = (const float*)d_in[2];
    const float* base_b0  = (const float*)d_in[3];
    const float* base_W1  = (const float*)d_in[4];
    const float* base_b1  = (const float*)d_in[5];
    const float* em_W0    = (const float*)d_in[6];
    const float* em_b0    = (const float*)d_in[7];
    const float* em_W1    = (const float*)d_in[8];
    const float* em_b1    = (const float*)d_in[9];
    const float* gate_W0  = (const float*)d_in[10];
    const float* gate_b0  = (const float*)d_in[11];
    const float* gate_W1  = (const float*)d_in[12];
    const float* gate_b1  = (const float*)d_in[13];
    const float* fc_W     = (const float*)d_in[14];
    const float* fc_b     = (const float*)d_in[15];
    const float* last_W   = (const float*)d_in[16];
    const float* last_b   = (const float*)d_in[17];
    float* out = (float*)d_out;

    float *h0, *base, *eh, *gin, *gh, *logits, *gates;
    float *o0, *o1, *o2, *o3, *inp, *last;
    __nv_bfloat16 *wbh, *wbl, *gwh, *gwl;
    cudaGetSymbolAddress((void**)&h0,   g_h0);
    cudaGetSymbolAddress((void**)&base, g_base);
    cudaGetSymbolAddress((void**)&eh,   g_eh);
    cudaGetSymbolAddress((void**)&gin,  g_gin);
    cudaGetSymbolAddress((void**)&gh,   g_gh);
    cudaGetSymbolAddress((void**)&logits, g_logits);
    cudaGetSymbolAddress((void**)&gates,  g_gates);
    cudaGetSymbolAddress((void**)&o0,  g_out0);
    cudaGetSymbolAddress((void**)&o1,  g_out1);
    cudaGetSymbolAddress((void**)&o2,  g_out2);
    cudaGetSymbolAddress((void**)&o3,  g_out3);
    cudaGetSymbolAddress((void**)&inp, g_inp);
    cudaGetSymbolAddress((void**)&last, g_last);
    cudaGetSymbolAddress((void**)&wbh,  g_wbh);
    cudaGetSymbolAddress((void**)&wbl,  g_wbl);
    cudaGetSymbolAddress((void**)&gwh,  g_gwh);
    cudaGetSymbolAddress((void**)&gwl,  g_gwl);

    // allow 80KB dynamic smem on all tc_gemm instantiations (host-side, idempotent)
    cudaFuncSetAttribute(tc_gemm_kernel<false, true,  false>, cudaFuncAttributeMaxDynamicSharedMemorySize, SMEM_DYN);
    cudaFuncSetAttribute(tc_gemm_kernel<false, false, false>, cudaFuncAttributeMaxDynamicSharedMemorySize, SMEM_DYN);
    cudaFuncSetAttribute(tc_gemm_kernel<false, true,  true >, cudaFuncAttributeMaxDynamicSharedMemorySize, SMEM_DYN);
    cudaFuncSetAttribute(tc_gemm_kernel<true,  true,  false>, cudaFuncAttributeMaxDynamicSharedMemorySize, SMEM_DYN);

    const int OFF_G  = BATCH * OUTD;
    const int OFF_OH = OFF_G + BATCH * GOUT;
    const int OFF_SM = OFF_OH + BATCH * GOUT;

    const dim3 blkT(32, 8);
    const dim3 gridTC(HDIM / 128, BATCH / 128);
    const dim3 gridTG(GH   / 128, BATCH / 128);

    // ---- weight prep ----
    tsplit_kernel<<<dim3(32, 2),  blkT>>>(base_W0, gwh + OFF_B0T, gwl + OFF_B0T, 64,   HDIM);
    tsplit_kernel<<<dim3(32, 32), blkT>>>(base_W1, gwh + OFF_B1T, gwl + OFF_B1T, HDIM, HDIM);
    tsplit_kernel<<<dim3(32, 8),  blkT>>>(em_W1,   gwh + OFF_EMT, gwl + OFF_EMT, EMH,  HDIM);
    tsplit_kernel<<<dim3(16, 32), blkT>>>(gate_W0, gwh + OFF_G0T, gwl + OFF_G0T, HDIM, GH);
    for (int m = 0; m < 4; m++)
        tsplit_kernel<<<dim3(32, 32), blkT>>>(fc_W + (u64)m * HDIM * HDIM,
                                              wbh + (u64)m * HDIM * HDIM,
                                              wbl + (u64)m * HDIM * HDIM, HDIM, HDIM);

    // ---- gating path (bf16x3 tensor) ----
    tc_gemm_kernel<false, true,  false><<<gridTC, 256, SMEM_DYN>>>(x, gwh + OFF_B0T, gwl + OFF_B0T, base_b0, nullptr, h0, HDIM, 64);
    tc_gemm_kernel<false, false, false><<<gridTC, 256, SMEM_DYN>>>(h0, gwh + OFF_B1T, gwl + OFF_B1T, base_b1, nullptr, base, HDIM, HDIM);
    ehidden_kernel<<<(BATCH * EMH + 255) / 256, 256>>>(em, em_W0, em_b0, eh);
    tc_gemm_kernel<false, true,  true ><<<gridTC, 256, SMEM_DYN>>>(eh, gwh + OFF_EMT, gwl + OFF_EMT, em_b1, base, gin, HDIM, EMH);
    tc_gemm_kernel<false, true,  false><<<gridTG, 256, SMEM_DYN>>>(gin, gwh + OFF_G0T, gwl + OFF_G0T, gate_b0, nullptr, gh, GH, HDIM);
    logits_kernel<<<(BATCH * 32 + 255) / 256, 256>>>(gh, gate_W1, gate_b1, logits);
    routing_kernel<<<(BATCH + 255) / 256, 256>>>(logits, gates, out + OFF_G, out + OFF_OH, out + OFF_SM);

    // ---- fc chain ----
    tc_gemm_kernel<true,  true, false><<<gridTC, 256, SMEM_DYN>>>(base, wbh + 0ull * HDIM * HDIM, wbl + 0ull * HDIM * HDIM, fc_b + 0 * HDIM, nullptr, o0, HDIM, HDIM);
    tc_gemm_kernel<false, true, false><<<gridTC, 256, SMEM_DYN>>>(o0,   wbh + 1ull * HDIM * HDIM, wbl + 1ull * HDIM * HDIM, fc_b + 1 * HDIM, nullptr, o1, HDIM, HDIM);
    wsum_kernel<<<(BATCH * HDIM / 4 + 255) / 256, 256>>>(gates, 1, 2, o0, o1, nullptr, nullptr, inp);
    tc_gemm_kernel<false, true, false><<<gridTC, 256, SMEM_DYN>>>(inp,  wbh + 2ull * HDIM * HDIM, wbl + 2ull * HDIM * HDIM, fc_b + 2 * HDIM, nullptr, o2, HDIM, HDIM);
    wsum_kernel<<<(BATCH * HDIM / 4 + 255) / 256, 256>>>(gates, 3, 3, o0, o1, o2, nullptr, inp);
    tc_gemm_kernel<false, true, false><<<gridTC, 256, SMEM_DYN>>>(inp,  wbh + 3ull * HDIM * HDIM, wbl + 3ull * HDIM * HDIM, fc_b + 3 * HDIM, nullptr, o3, HDIM, HDIM);
    wsum_kernel<<<(BATCH * HDIM / 4 + 255) / 256, 256>>>(gates, 6, 4, o0, o1, o2, o3, last);
    final_kernel<<<(BATCH * OUTD + 255) / 256, 256>>>(last, last_W, last_b, out);
}

// round 8
// speedup vs baseline: 2.6871x; 1.0477x over previous
#include <cuda_runtime.h>
#include <cuda_bf16.h>
#include <math.h>
#include <stdint.h>

#define BATCH 8192
#define HDIM  1024
#define GH    512
#define EMH   256
#define OUTD  18
#define GOUT  10

typedef unsigned long long u64;
typedef __nv_bfloat16 bf16;

// -------- scratch (device globals: allocation-free) --------
__device__ float g_base[BATCH*HDIM];
__device__ float g_gh  [BATCH*GH];
__device__ float g_logits[BATCH*GOUT];
__device__ float g_gates [BATCH*GOUT];
__device__ float g_out0[BATCH*HDIM];
__device__ float g_out1[BATCH*HDIM];
__device__ float g_out2[BATCH*HDIM];
__device__ float g_out3[BATCH*HDIM];
__device__ float g_last[BATCH*HDIM];
// activation splits (bf16 hi/lo pairs)
__device__ bf16 g_xh [BATCH*64],   g_xl [BATCH*64];
__device__ bf16 g_h0h[BATCH*HDIM], g_h0l[BATCH*HDIM];
__device__ bf16 g_bRh[BATCH*HDIM], g_bRl[BATCH*HDIM];   // relu(base) split
__device__ bf16 g_ehh[BATCH*EMH],  g_ehl[BATCH*EMH];
__device__ bf16 g_gnh[BATCH*HDIM], g_gnl[BATCH*HDIM];   // gate_in split
__device__ bf16 g_o0h[BATCH*HDIM], g_o0l[BATCH*HDIM];
__device__ bf16 g_iph[BATCH*HDIM], g_ipl[BATCH*HDIM];   // inp split
// weight splits
__device__ bf16 g_wbh[4*HDIM*HDIM], g_wbl[4*HDIM*HDIM]; // fc [mod][N][K]
__device__ bf16 g_gwh[2*HDIM*HDIM], g_gwl[2*HDIM*HDIM]; // gating (transposed)

#define OFF_B0T 0
#define OFF_B1T (OFF_B0T + 1024*64)
#define OFF_EMT (OFF_B1T + 1024*1024)
#define OFF_G0T (OFF_EMT + 1024*256)

__device__ __forceinline__ void split2(float a, float b, uint32_t &hi, uint32_t &lo) {
    bf16 ha = __float2bfloat16(a), hb = __float2bfloat16(b);
    bf16 la = __float2bfloat16(a - __bfloat162float(ha));
    bf16 lb = __float2bfloat16(b - __bfloat162float(hb));
    hi = (uint32_t)__bfloat16_as_ushort(ha) | ((uint32_t)__bfloat16_as_ushort(hb) << 16);
    lo = (uint32_t)__bfloat16_as_ushort(la) | ((uint32_t)__bfloat16_as_ushort(lb) << 16);
}

// =====================================================================
// bf16x3 split tensor-core GEMM, fully cp.async pipelined:
//   C = epi( Asplit @ Wt^T + bias ),  A given pre-split bf16 hi/lo [M][K]
// CTA 128x128, K-slab 32, 8 warps (4Mx2N), warp tile 32x64.
// Epilogue writes fp32 and/or a bf16 hi/lo split of the (optionally
// relu'd) result for downstream GEMM consumption.
// =====================================================================
#define TCK 32
#define STR 40
#define ARR 5120                    // elems per array (128*STR)
#define BUFB 40960                  // bytes per buffer (4 arrays)
#define SMEM_DYN (2*BUFB)

#define CPASYNC16(dst, src) \
    asm volatile("cp.async.ca.shared.global [%0], [%1], 16;" :: "r"(dst), "l"(src))
#define CPCOMMIT() asm volatile("cp.async.commit_group;" ::: "memory")
#define CPWAIT0()  asm volatile("cp.async.wait_group 0;"  ::: "memory")
#define LDSM4(r0, r1, r2, r3, addr) \
    asm volatile("ldmatrix.sync.aligned.m8n8.x4.shared.b16 {%0,%1,%2,%3}, [%4];" \
                 : "=r"(r0), "=r"(r1), "=r"(r2), "=r"(r3) : "r"(addr))

__device__ __forceinline__ void mma16816(float c[4], const uint32_t a[4],
                                         uint32_t b0, uint32_t b1) {
    asm("mma.sync.aligned.m16n8k16.row.col.f32.bf16.bf16.f32 "
        "{%0,%1,%2,%3}, {%4,%5,%6,%7}, {%8,%9}, {%0,%1,%2,%3};"
        : "+f"(c[0]), "+f"(c[1]), "+f"(c[2]), "+f"(c[3])
        : "r"(a[0]), "r"(a[1]), "r"(a[2]), "r"(a[3]), "r"(b0), "r"(b1));
}

template<bool MUL_C, bool RELU_C, bool WRITE_F32, bool WRITE_SPLIT, bool SPLIT_RELU>
__global__ __launch_bounds__(256, 2)
void tc_gemm_kernel(const bf16* __restrict__ Ah_, const bf16* __restrict__ Al_,
                    const bf16* __restrict__ Wh,  const bf16* __restrict__ Wl,
                    const float* __restrict__ bias, const float* __restrict__ Cmul,
                    float* __restrict__ C, bf16* __restrict__ Chi, bf16* __restrict__ Clo,
                    int N, int K)
{
    extern __shared__ uint16_t dsm[];
    const uint32_t smem_u = (uint32_t)__cvta_generic_to_shared(dsm);

    const int tid  = threadIdx.x;
    const int wid  = tid >> 5;
    const int lane = tid & 31;
    const int g = lane >> 2;
    const int t = lane & 3;
    const int warp_m = wid & 3;
    const int warp_n = wid >> 2;
    const int bm = blockIdx.y * 128;
    const int bn = blockIdx.x * 128;

    const int srow = tid >> 1;
    const int kh   = (tid & 1) * 16;
    const uint32_t sbyte = (uint32_t)(srow * STR + kh) * 2;

    const bf16* Ahp = Ah_ + (u64)(bm + srow) * K + kh;
    const bf16* Alp = Al_ + (u64)(bm + srow) * K + kh;
    const bf16* Bhp = Wh  + (u64)(bn + srow) * K + kh;
    const bf16* Blp = Wl  + (u64)(bn + srow) * K + kh;

    uint32_t aOff[2], bOff[4];
#pragma unroll
    for (int mt = 0; mt < 2; mt++)
        aOff[mt] = (uint32_t)(((warp_m * 32 + mt * 16 + (lane & 15)) * STR
                              + ((lane >> 4) & 1) * 8) * 2);
#pragma unroll
    for (int np = 0; np < 4; np++)
        bOff[np] = (uint32_t)(((warp_n * 64 + np * 16 + ((lane >> 4) & 1) * 8 + (lane & 7)) * STR
                              + ((lane >> 3) & 1) * 8) * 2);

    float acc[2][8][4];
#pragma unroll
    for (int mt = 0; mt < 2; mt++)
#pragma unroll
        for (int nt = 0; nt < 8; nt++)
#pragma unroll
            for (int e = 0; e < 4; e++) acc[mt][nt][e] = 0.f;

    const int nslab = K / TCK;

    auto stage = [&](int s, int p) {
        const uint32_t b0 = smem_u + p * BUFB;
        const bf16* ah = Ahp + s * TCK;
        const bf16* al = Alp + s * TCK;
        const bf16* bh = Bhp + s * TCK;
        const bf16* bl = Blp + s * TCK;
        CPASYNC16(b0 + sbyte,                ah);
        CPASYNC16(b0 + sbyte + 16,           ah + 8);
        CPASYNC16(b0 + 2 * ARR + sbyte,      al);
        CPASYNC16(b0 + 2 * ARR + sbyte + 16, al + 8);
        CPASYNC16(b0 + 4 * ARR + sbyte,      bh);
        CPASYNC16(b0 + 4 * ARR + sbyte + 16, bh + 8);
        CPASYNC16(b0 + 6 * ARR + sbyte,      bl);
        CPASYNC16(b0 + 6 * ARR + sbyte + 16, bl + 8);
    };

    stage(0, 0);
    CPCOMMIT();
    CPWAIT0();
    __syncthreads();

    for (int s = 0; s < nslab; s++) {
        const int p = s & 1;
        if (s + 1 < nslab) {
            stage(s + 1, p ^ 1);
            CPCOMMIT();
        }

        const uint32_t pb = smem_u + p * BUFB;
#pragma unroll
        for (int kk = 0; kk < 2; kk++) {
            const uint32_t ko = kk * 32;
            uint32_t ah[2][4], al[2][4];
            LDSM4(ah[0][0], ah[0][1], ah[0][2], ah[0][3], pb + aOff[0] + ko);
            LDSM4(ah[1][0], ah[1][1], ah[1][2], ah[1][3], pb + aOff[1] + ko);
            LDSM4(al[0][0], al[0][1], al[0][2], al[0][3], pb + 2 * ARR + aOff[0] + ko);
            LDSM4(al[1][0], al[1][1], al[1][2], al[1][3], pb + 2 * ARR + aOff[1] + ko);
#pragma unroll
            for (int np = 0; np < 4; np++) {
                uint32_t bh[4], bl[4];
                LDSM4(bh[0], bh[1], bh[2], bh[3], pb + 4 * ARR + bOff[np] + ko);
                LDSM4(bl[0], bl[1], bl[2], bl[3], pb + 6 * ARR + bOff[np] + ko);
#pragma unroll
                for (int mt = 0; mt < 2; mt++) {
                    mma16816(acc[mt][2 * np + 0], ah[mt], bh[0], bh[1]);
                    mma16816(acc[mt][2 * np + 0], ah[mt], bl[0], bl[1]);
                    mma16816(acc[mt][2 * np + 0], al[mt], bh[0], bh[1]);
                    mma16816(acc[mt][2 * np + 1], ah[mt], bh[2], bh[3]);
                    mma16816(acc[mt][2 * np + 1], ah[mt], bl[2], bl[3]);
                    mma16816(acc[mt][2 * np + 1], al[mt], bh[2], bh[3]);
                }
            }
        }
        CPWAIT0();
        __syncthreads();
    }

    // ---- epilogue ----
#pragma unroll
    for (int mt = 0; mt < 2; mt++) {
#pragma unroll
        for (int nt = 0; nt < 8; nt++) {
            const int row = bm + warp_m * 32 + mt * 16 + g;
            const int col = bn + warp_n * 64 + nt * 8 + t * 2;
            const float b0 = bias[col], b1 = bias[col + 1];
            float2 v0, v1;
            v0.x = acc[mt][nt][0] + b0;
            v0.y = acc[mt][nt][1] + b1;
            v1.x = acc[mt][nt][2] + b0;
            v1.y = acc[mt][nt][3] + b1;
            if (RELU_C) {
                v0.x = fmaxf(v0.x, 0.f); v0.y = fmaxf(v0.y, 0.f);
                v1.x = fmaxf(v1.x, 0.f); v1.y = fmaxf(v1.y, 0.f);
            }
            if (MUL_C) {
                float2 m0 = *(const float2*)(Cmul + (u64)row * N + col);
                float2 m1 = *(const float2*)(Cmul + (u64)(row + 8) * N + col);
                v0.x *= m0.x; v0.y *= m0.y;
                v1.x *= m1.x; v1.y *= m1.y;
            }
            if (WRITE_F32) {
                *(float2*)(C + (u64)row * N + col)       = v0;
                *(float2*)(C + (u64)(row + 8) * N + col) = v1;
            }
            if (WRITE_SPLIT) {
                float2 w0 = v0, w1 = v1;
                if (SPLIT_RELU) {
                    w0.x = fmaxf(w0.x, 0.f); w0.y = fmaxf(w0.y, 0.f);
                    w1.x = fmaxf(w1.x, 0.f); w1.y = fmaxf(w1.y, 0.f);
                }
                uint32_t h0, l0, h1, l1;
                split2(w0.x, w0.y, h0, l0);
                split2(w1.x, w1.y, h1, l1);
                *(uint32_t*)(Chi + (u64)row * N + col)       = h0;
                *(uint32_t*)(Clo + (u64)row * N + col)       = l0;
                *(uint32_t*)(Chi + (u64)(row + 8) * N + col) = h1;
                *(uint32_t*)(Clo + (u64)(row + 8) * N + col) = l1;
            }
        }
    }
}

// transpose + bf16-split: W [K,N] fp32 -> Wh/Wl [N,K] bf16
__global__ void tsplit_kernel(const float* __restrict__ W,
                              bf16* __restrict__ Wh, bf16* __restrict__ Wl,
                              int K, int N)
{
    __shared__ float tile[32][33];
    const int k0 = blockIdx.y * 32, n0 = blockIdx.x * 32;
    const int tx = threadIdx.x, ty = threadIdx.y;
#pragma unroll
    for (int i = 0; i < 32; i += 8)
        tile[ty + i][tx] = W[(u64)(k0 + ty + i) * N + n0 + tx];
    __syncthreads();
#pragma unroll
    for (int i = 0; i < 32; i += 8) {
        float v = tile[tx][ty + i];
        bf16 h = __float2bfloat16(v);
        bf16 l = __float2bfloat16(v - __bfloat162float(h));
        Wh[(u64)(n0 + ty + i) * K + k0 + tx] = h;
        Wl[(u64)(n0 + ty + i) * K + k0 + tx] = l;
    }
}

// elementwise split: src fp32 -> hi/lo bf16
__global__ void asplit_kernel(const float* __restrict__ src,
                              bf16* __restrict__ hi, bf16* __restrict__ lo, int n)
{
    int idx = blockIdx.x * blockDim.x + threadIdx.x;
    if (idx >= n) return;
    float v = src[idx];
    bf16 h = __float2bfloat16(v);
    hi[idx] = h;
    lo[idx] = __float2bfloat16(v - __bfloat162float(h));
}

// em hidden: split(relu(em[b]*em_W0[j] + em_b0[j]))
__global__ void ehidden_kernel(const float* __restrict__ em, const float* __restrict__ W0,
                               const float* __restrict__ b0,
                               bf16* __restrict__ hi, bf16* __restrict__ lo)
{
    int idx = blockIdx.x * blockDim.x + threadIdx.x;
    if (idx >= BATCH * EMH) return;
    int b = idx >> 8;
    int j = idx & (EMH - 1);
    float v = fmaxf(em[b] * W0[j] + b0[j], 0.f);
    bf16 h = __float2bfloat16(v);
    hi[idx] = h;
    lo[idx] = __float2bfloat16(v - __bfloat162float(h));
}

// logits = gate_h @ gate_W1 + gate_b1  (warp-per-row, shuffle reduce, fp32)
__global__ void logits_kernel(const float* __restrict__ gh, const float* __restrict__ W,
                              const float* __restrict__ b, float* __restrict__ logits)
{
    int warp = (blockIdx.x * blockDim.x + threadIdx.x) >> 5;
    int lane = threadIdx.x & 31;
    if (warp >= BATCH) return;
    const float* g = gh + warp * GH;
    float acc[GOUT];
#pragma unroll
    for (int j = 0; j < GOUT; j++) acc[j] = 0.f;
    for (int k = lane; k < GH; k += 32) {
        float gv = g[k];
        const float* wr = W + k * GOUT;
#pragma unroll
        for (int j = 0; j < GOUT; j++) acc[j] += gv * wr[j];
    }
#pragma unroll
    for (int j = 0; j < GOUT; j++) {
#pragma unroll
        for (int o = 16; o > 0; o >>= 1)
            acc[j] += __shfl_xor_sync(0xffffffffu, acc[j], o);
    }
    if (lane == 0) {
        float* dst = logits + warp * GOUT;
#pragma unroll
        for (int j = 0; j < GOUT; j++) dst[j] = acc[j] + b[j];
    }
}

// Routing: top-2 + softmax gates per module group
__device__ __forceinline__ void route_m(const float* l, int m,
                                        float* g, float* oh, float* sm)
{
    float mx = l[0];
    for (int i = 1; i < m; i++) mx = fmaxf(mx, l[i]);
    float e[4], s = 0.f;
    for (int i = 0; i < m; i++) { e[i] = expf(l[i] - mx); s += e[i]; }
    float inv = 1.f / s;
    for (int i = 0; i < m; i++) sm[i] = e[i] * inv;
    int i1 = 0;
    for (int i = 1; i < m; i++) if (l[i] > l[i1]) i1 = i;
    int i2 = -1;
    for (int i = 0; i < m; i++) {
        if (i == i1) continue;
        if (i2 < 0 || l[i] > l[i2]) i2 = i;
    }
    float m2 = fmaxf(l[i1], l[i2]);
    float ea = expf(l[i1] - m2), eb = expf(l[i2] - m2);
    float si = 1.f / (ea + eb);
    g[i1] = ea * si; g[i2] = eb * si;
    oh[i1] = 1.f; oh[i2] = 1.f;
}

__global__ void routing_kernel(const float* __restrict__ logits, float* __restrict__ gdev,
                               float* __restrict__ og, float* __restrict__ ooh,
                               float* __restrict__ osm)
{
    int b = blockIdx.x * blockDim.x + threadIdx.x;
    if (b >= BATCH) return;
    float l[GOUT];
#pragma unroll
    for (int i = 0; i < GOUT; i++) l[i] = logits[b * GOUT + i];
    float g[GOUT], oh[GOUT], sm[GOUT];
#pragma unroll
    for (int i = 0; i < GOUT; i++) { g[i] = 0.f; oh[i] = 0.f; sm[i] = 0.f; }
    g[0] = 1.f; oh[0] = 1.f; sm[0] = 1.f;
    route_m(l + 1, 2, g + 1, oh + 1, sm + 1);
    route_m(l + 3, 3, g + 3, oh + 3, sm + 3);
    route_m(l + 6, 4, g + 6, oh + 6, sm + 6);
#pragma unroll
    for (int i = 0; i < GOUT; i++) {
        gdev[b * GOUT + i] = g[i];
        og  [b * GOUT + i] = g[i];
        ooh [b * GOUT + i] = oh[i];
        osm [b * GOUT + i] = sm[i];
    }
}

// dst = sum_t gates[b, goff+t] * o_t[b,:]; writes split bf16 (dsth/dstl) or fp32 (dstf)
__global__ void wsum_kernel(const float* __restrict__ gates, int goff, int nt,
                            const float* __restrict__ o0, const float* __restrict__ o1,
                            const float* __restrict__ o2, const float* __restrict__ o3,
                            float* __restrict__ dstf,
                            bf16* __restrict__ dsth, bf16* __restrict__ dstl)
{
    int idx = blockIdx.x * blockDim.x + threadIdx.x;
    if (idx >= BATCH * (HDIM / 4)) return;
    int b = idx / (HDIM / 4);
    const float* g = gates + b * GOUT + goff;
    float4 r = make_float4(0.f, 0.f, 0.f, 0.f);
    float w; float4 v;
    w = g[0]; v = ((const float4*)o0)[idx];
    r.x += w * v.x; r.y += w * v.y; r.z += w * v.z; r.w += w * v.w;
    if (nt > 1) {
        w = g[1]; v = ((const float4*)o1)[idx];
        r.x += w * v.x; r.y += w * v.y; r.z += w * v.z; r.w += w * v.w;
    }
    if (nt > 2) {
        w = g[2]; v = ((const float4*)o2)[idx];
        r.x += w * v.x; r.y += w * v.y; r.z += w * v.z; r.w += w * v.w;
    }
    if (nt > 3) {
        w = g[3]; v = ((const float4*)o3)[idx];
        r.x += w * v.x; r.y += w * v.y; r.z += w * v.z; r.w += w * v.w;
    }
    if (dstf) {
        ((float4*)dstf)[idx] = r;
    } else {
        uint32_t h0, l0, h1, l1;
        split2(r.x, r.y, h0, l0);
        split2(r.z, r.w, h1, l1);
        uint2 hv = make_uint2(h0, h1), lv = make_uint2(l0, l1);
        ((uint2*)dsth)[idx] = hv;
        ((uint2*)dstl)[idx] = lv;
    }
}

// final = last_buf @ last_W + last_b   (N=18)
__global__ void final_kernel(const float* __restrict__ last, const float* __restrict__ W,
                             const float* __restrict__ b, float* __restrict__ out)
{
    int idx = blockIdx.x * blockDim.x + threadIdx.x;
    if (idx >= BATCH * OUTD) return;
    int row = idx / OUTD, o = idx % OUTD;
    const float4* lp = (const float4*)(last + row * HDIM);
    float s = 0.f;
    for (int k = 0; k < HDIM / 4; k++) {
        float4 v = lp[k];
        s += v.x * W[(4 * k + 0) * OUTD + o];
        s += v.y * W[(4 * k + 1) * OUTD + o];
        s += v.z * W[(4 * k + 2) * OUTD + o];
        s += v.w * W[(4 * k + 3) * OUTD + o];
    }
    out[idx] = s + b[o];
}

extern "C" void kernel_launch(void* const* d_in, const int* in_sizes, int n_in,
                              void* d_out, int out_size)
{
    const float* x        = (const float*)d_in[0];
    const float* em       = (const float*)d_in[1];
    const float* base_W0  = (const float*)d_in[2];
    const float* base_b0  = (const float*)d_in[3];
    const float* base_W1  = (const float*)d_in[4];
    const float* base_b1  = (const float*)d_in[5];
    const float* em_W0    = (const float*)d_in[6];
    const float* em_b0    = (const float*)d_in[7];
    const float* em_W1    = (const float*)d_in[8];
    const float* em_b1    = (const float*)d_in[9];
    const float* gate_W0  = (const float*)d_in[10];
    const float* gate_b0  = (const float*)d_in[11];
    const float* gate_W1  = (const float*)d_in[12];
    const float* gate_b1  = (const float*)d_in[13];
    const float* fc_W     = (const float*)d_in[14];
    const float* fc_b     = (const float*)d_in[15];
    const float* last_W   = (const float*)d_in[16];
    const float* last_b   = (const float*)d_in[17];
    float* out = (float*)d_out;

    float *base, *gh, *logits, *gates, *o0, *o1, *o2, *o3, *last;
    bf16 *xh, *xl, *h0h, *h0l, *bRh, *bRl, *ehh, *ehl, *gnh, *gnl;
    bf16 *o0h, *o0l, *iph, *ipl, *wbh, *wbl, *gwh, *gwl;
    cudaGetSymbolAddress((void**)&base, g_base);
    cudaGetSymbolAddress((void**)&gh,   g_gh);
    cudaGetSymbolAddress((void**)&logits, g_logits);
    cudaGetSymbolAddress((void**)&gates,  g_gates);
    cudaGetSymbolAddress((void**)&o0,  g_out0);
    cudaGetSymbolAddress((void**)&o1,  g_out1);
    cudaGetSymbolAddress((void**)&o2,  g_out2);
    cudaGetSymbolAddress((void**)&o3,  g_out3);
    cudaGetSymbolAddress((void**)&last, g_last);
    cudaGetSymbolAddress((void**)&xh,  g_xh);  cudaGetSymbolAddress((void**)&xl,  g_xl);
    cudaGetSymbolAddress((void**)&h0h, g_h0h); cudaGetSymbolAddress((void**)&h0l, g_h0l);
    cudaGetSymbolAddress((void**)&bRh, g_bRh); cudaGetSymbolAddress((void**)&bRl, g_bRl);
    cudaGetSymbolAddress((void**)&ehh, g_ehh); cudaGetSymbolAddress((void**)&ehl, g_ehl);
    cudaGetSymbolAddress((void**)&gnh, g_gnh); cudaGetSymbolAddress((void**)&gnl, g_gnl);
    cudaGetSymbolAddress((void**)&o0h, g_o0h); cudaGetSymbolAddress((void**)&o0l, g_o0l);
    cudaGetSymbolAddress((void**)&iph, g_iph); cudaGetSymbolAddress((void**)&ipl, g_ipl);
    cudaGetSymbolAddress((void**)&wbh, g_wbh); cudaGetSymbolAddress((void**)&wbl, g_wbl);
    cudaGetSymbolAddress((void**)&gwh, g_gwh); cudaGetSymbolAddress((void**)&gwl, g_gwl);

    cudaFuncSetAttribute(tc_gemm_kernel<false, true,  false, true,  false>, cudaFuncAttributeMaxDynamicSharedMemorySize, SMEM_DYN);
    cudaFuncSetAttribute(tc_gemm_kernel<false, false, true,  true,  true >, cudaFuncAttributeMaxDynamicSharedMemorySize, SMEM_DYN);
    cudaFuncSetAttribute(tc_gemm_kernel<true,  true,  false, true,  false>, cudaFuncAttributeMaxDynamicSharedMemorySize, SMEM_DYN);
    cudaFuncSetAttribute(tc_gemm_kernel<false, true,  true,  false, false>, cudaFuncAttributeMaxDynamicSharedMemorySize, SMEM_DYN);
    cudaFuncSetAttribute(tc_gemm_kernel<false, true,  true,  true,  false>, cudaFuncAttributeMaxDynamicSharedMemorySize, SMEM_DYN);

    const int OFF_G  = BATCH * OUTD;
    const int OFF_OH = OFF_G + BATCH * GOUT;
    const int OFF_SM = OFF_OH + BATCH * GOUT;

    const dim3 blkT(32, 8);
    const dim3 gridTC(HDIM / 128, BATCH / 128);
    const dim3 gridTG(GH   / 128, BATCH / 128);

    // ---- prep: weight + input splits ----
    tsplit_kernel<<<dim3(32, 2),  blkT>>>(base_W0, gwh + OFF_B0T, gwl + OFF_B0T, 64,   HDIM);
    tsplit_kernel<<<dim3(32, 32), blkT>>>(base_W1, gwh + OFF_B1T, gwl + OFF_B1T, HDIM, HDIM);
    tsplit_kernel<<<dim3(32, 8),  blkT>>>(em_W1,   gwh + OFF_EMT, gwl + OFF_EMT, EMH,  HDIM);
    tsplit_kernel<<<dim3(16, 32), blkT>>>(gate_W0, gwh + OFF_G0T, gwl + OFF_G0T, HDIM, GH);
    for (int m = 0; m < 4; m++)
        tsplit_kernel<<<dim3(32, 32), blkT>>>(fc_W + (u64)m * HDIM * HDIM,
                                              wbh + (u64)m * HDIM * HDIM,
                                              wbl + (u64)m * HDIM * HDIM, HDIM, HDIM);
    asplit_kernel<<<(BATCH * 64 + 255) / 256, 256>>>(x, xh, xl, BATCH * 64);

    // ---- gating path ----
    // h0 = relu(x @ base_W0 + b0)                [split out only]
    tc_gemm_kernel<false, true,  false, true,  false><<<gridTC, 256, SMEM_DYN>>>(xh, xl, gwh + OFF_B0T, gwl + OFF_B0T, base_b0, nullptr, nullptr, h0h, h0l, HDIM, 64);
    // base = h0 @ base_W1 + b1                   [f32 out + split(relu)]
    tc_gemm_kernel<false, false, true,  true,  true ><<<gridTC, 256, SMEM_DYN>>>(h0h, h0l, gwh + OFF_B1T, gwl + OFF_B1T, base_b1, nullptr, base, bRh, bRl, HDIM, HDIM);
    ehidden_kernel<<<(BATCH * EMH + 255) / 256, 256>>>(em, em_W0, em_b0, ehh, ehl);
    // gin = relu(eh @ em_W1 + em_b1) * base      [split out only]
    tc_gemm_kernel<true,  true,  false, true,  false><<<gridTC, 256, SMEM_DYN>>>(ehh, ehl, gwh + OFF_EMT, gwl + OFF_EMT, em_b1, base, nullptr, gnh, gnl, HDIM, EMH);
    // gh = relu(gin @ gate_W0 + gate_b0)         [f32 out]
    tc_gemm_kernel<false, true,  true,  false, false><<<gridTG, 256, SMEM_DYN>>>(gnh, gnl, gwh + OFF_G0T, gwl + OFF_G0T, gate_b0, nullptr, gh, nullptr, nullptr, GH, HDIM);
    logits_kernel<<<(BATCH * 32 + 255) / 256, 256>>>(gh, gate_W1, gate_b1, logits);
    routing_kernel<<<(BATCH + 255) / 256, 256>>>(logits, gates, out + OFF_G, out + OFF_OH, out + OFF_SM);

    // ---- fc chain ----
    // o0 = relu(relu(base) @ fc0 + b)            [f32 + split]
    tc_gemm_kernel<false, true,  true,  true,  false><<<gridTC, 256, SMEM_DYN>>>(bRh, bRl, wbh + 0ull * HDIM * HDIM, wbl + 0ull * HDIM * HDIM, fc_b + 0 * HDIM, nullptr, o0, o0h, o0l, HDIM, HDIM);
    // o1 = relu(o0 @ fc1 + b)                    [f32 out]
    tc_gemm_kernel<false, true,  true,  false, false><<<gridTC, 256, SMEM_DYN>>>(o0h, o0l, wbh + 1ull * HDIM * HDIM, wbl + 1ull * HDIM * HDIM, fc_b + 1 * HDIM, nullptr, o1, nullptr, nullptr, HDIM, HDIM);
    wsum_kernel<<<(BATCH * HDIM / 4 + 255) / 256, 256>>>(gates, 1, 2, o0, o1, nullptr, nullptr, nullptr, iph, ipl);
    tc_gemm_kernel<false, true,  true,  false, false><<<gridTC, 256, SMEM_DYN>>>(iph, ipl, wbh + 2ull * HDIM * HDIM, wbl + 2ull * HDIM * HDIM, fc_b + 2 * HDIM, nullptr, o2, nullptr, nullptr, HDIM, HDIM);
    wsum_kernel<<<(BATCH * HDIM / 4 + 255) / 256, 256>>>(gates, 3, 3, o0, o1, o2, nullptr, nullptr, iph, ipl);
    tc_gemm_kernel<false, true,  true,  false, false><<<gridTC, 256, SMEM_DYN>>>(iph, ipl, wbh + 3ull * HDIM * HDIM, wbl + 3ull * HDIM * HDIM, fc_b + 3 * HDIM, nullptr, o3, nullptr, nullptr, HDIM, HDIM);
    wsum_kernel<<<(BATCH * HDIM / 4 + 255) / 256, 256>>>(gates, 6, 4, o0, o1, o2, o3, last, nullptr, nullptr);
    final_kernel<<<(BATCH * OUTD + 255) / 256, 256>>>(last, last_W, last_b, out);
}

// round 9
// speedup vs baseline: 2.8435x; 1.0582x over previous
#include <cuda_runtime.h>
#include <cuda_bf16.h>
#include <math.h>
#include <stdint.h>

#define BATCH 8192
#define HDIM  1024
#define GH    512
#define EMH   256
#define OUTD  18
#define GOUT  10

typedef unsigned long long u64;
typedef __nv_bfloat16 bf16;

// -------- scratch (device globals: allocation-free) --------
__device__ float g_base[BATCH*HDIM];
__device__ float g_gh  [BATCH*GH];
__device__ float g_logits[BATCH*GOUT];
__device__ float g_gates [BATCH*GOUT];
__device__ float g_out0[BATCH*HDIM];
__device__ float g_out1[BATCH*HDIM];
__device__ float g_out2[BATCH*HDIM];
__device__ float g_last[BATCH*HDIM];
// activation splits (bf16 hi/lo pairs)
__device__ bf16 g_xh [BATCH*64],   g_xl [BATCH*64];
__device__ bf16 g_h0h[BATCH*HDIM], g_h0l[BATCH*HDIM];
__device__ bf16 g_bRh[BATCH*HDIM], g_bRl[BATCH*HDIM];
__device__ bf16 g_ehh[BATCH*EMH],  g_ehl[BATCH*EMH];
__device__ bf16 g_gnh[BATCH*HDIM], g_gnl[BATCH*HDIM];
__device__ bf16 g_o0h[BATCH*HDIM], g_o0l[BATCH*HDIM];
__device__ bf16 g_iph[BATCH*HDIM], g_ipl[BATCH*HDIM];
// weight splits
__device__ bf16 g_wbh[4*HDIM*HDIM], g_wbl[4*HDIM*HDIM];
__device__ bf16 g_gwh[2*HDIM*HDIM], g_gwl[2*HDIM*HDIM];

#define OFF_B0T 0
#define OFF_B1T (OFF_B0T + 1024*64)
#define OFF_EMT (OFF_B1T + 1024*1024)
#define OFF_G0T (OFF_EMT + 1024*256)

__device__ __forceinline__ void split2(float a, float b, uint32_t &hi, uint32_t &lo) {
    bf16 ha = __float2bfloat16(a), hb = __float2bfloat16(b);
    bf16 la = __float2bfloat16(a - __bfloat162float(ha));
    bf16 lb = __float2bfloat16(b - __bfloat162float(hb));
    hi = (uint32_t)__bfloat16_as_ushort(ha) | ((uint32_t)__bfloat16_as_ushort(hb) << 16);
    lo = (uint32_t)__bfloat16_as_ushort(la) | ((uint32_t)__bfloat16_as_ushort(lb) << 16);
}

// =====================================================================
// bf16x3 split tensor-core GEMM, cp.async pipelined, fused epilogues.
// CTA 128x128, K-slab 32, 8 warps (4Mx2N), warp tile 32x64.
// WSUM>0: epilogue also computes gated weighted sum of prior outputs
// P0..P2 and its own (relu'd) result; WSUM<4 -> split out, ==4 -> f32 Cw.
// =====================================================================
#define TCK 32
#define STR 40
#define ARR 5120
#define BUFB 40960
#define SMEM_DYN (2*BUFB)

#define CPASYNC16(dst, src) \
    asm volatile("cp.async.ca.shared.global [%0], [%1], 16;" :: "r"(dst), "l"(src))
#define CPCOMMIT() asm volatile("cp.async.commit_group;" ::: "memory")
#define CPWAIT0()  asm volatile("cp.async.wait_group 0;"  ::: "memory")
#define LDSM4(r0, r1, r2, r3, addr) \
    asm volatile("ldmatrix.sync.aligned.m8n8.x4.shared.b16 {%0,%1,%2,%3}, [%4];" \
                 : "=r"(r0), "=r"(r1), "=r"(r2), "=r"(r3) : "r"(addr))

__device__ __forceinline__ void mma16816(float c[4], const uint32_t a[4],
                                         uint32_t b0, uint32_t b1) {
    asm("mma.sync.aligned.m16n8k16.row.col.f32.bf16.bf16.f32 "
        "{%0,%1,%2,%3}, {%4,%5,%6,%7}, {%8,%9}, {%0,%1,%2,%3};"
        : "+f"(c[0]), "+f"(c[1]), "+f"(c[2]), "+f"(c[3])
        : "r"(a[0]), "r"(a[1]), "r"(a[2]), "r"(a[3]), "r"(b0), "r"(b1));
}

template<bool MUL_C, bool RELU_C, bool WRITE_F32, bool WRITE_SPLIT, bool SPLIT_RELU, int WSUM>
__global__ __launch_bounds__(256, 2)
void tc_gemm_kernel(const bf16* __restrict__ Ah_, const bf16* __restrict__ Al_,
                    const bf16* __restrict__ Wh,  const bf16* __restrict__ Wl,
                    const float* __restrict__ bias, const float* __restrict__ Cmul,
                    float* __restrict__ C, bf16* __restrict__ Chi, bf16* __restrict__ Clo,
                    float* __restrict__ Cw, const float* __restrict__ gsum, int goff,
                    const float* __restrict__ P0, const float* __restrict__ P1,
                    const float* __restrict__ P2,
                    int N, int K)
{
    extern __shared__ uint16_t dsm[];
    const uint32_t smem_u = (uint32_t)__cvta_generic_to_shared(dsm);

    const int tid  = threadIdx.x;
    const int wid  = tid >> 5;
    const int lane = tid & 31;
    const int g = lane >> 2;
    const int t = lane & 3;
    const int warp_m = wid & 3;
    const int warp_n = wid >> 2;
    const int bm = blockIdx.y * 128;
    const int bn = blockIdx.x * 128;

    const int srow = tid >> 1;
    const int kh   = (tid & 1) * 16;
    const uint32_t sbyte = (uint32_t)(srow * STR + kh) * 2;

    const bf16* Ahp = Ah_ + (u64)(bm + srow) * K + kh;
    const bf16* Alp = Al_ + (u64)(bm + srow) * K + kh;
    const bf16* Bhp = Wh  + (u64)(bn + srow) * K + kh;
    const bf16* Blp = Wl  + (u64)(bn + srow) * K + kh;

    uint32_t aOff[2], bOff[4];
#pragma unroll
    for (int mt = 0; mt < 2; mt++)
        aOff[mt] = (uint32_t)(((warp_m * 32 + mt * 16 + (lane & 15)) * STR
                              + ((lane >> 4) & 1) * 8) * 2);
#pragma unroll
    for (int np = 0; np < 4; np++)
        bOff[np] = (uint32_t)(((warp_n * 64 + np * 16 + ((lane >> 4) & 1) * 8 + (lane & 7)) * STR
                              + ((lane >> 3) & 1) * 8) * 2);

    float acc[2][8][4];
#pragma unroll
    for (int mt = 0; mt < 2; mt++)
#pragma unroll
        for (int nt = 0; nt < 8; nt++)
#pragma unroll
            for (int e = 0; e < 4; e++) acc[mt][nt][e] = 0.f;

    const int nslab = K / TCK;

    auto stage = [&](int s, int p) {
        const uint32_t b0 = smem_u + p * BUFB;
        const bf16* ah = Ahp + s * TCK;
        const bf16* al = Alp + s * TCK;
        const bf16* bh = Bhp + s * TCK;
        const bf16* bl = Blp + s * TCK;
        CPASYNC16(b0 + sbyte,                ah);
        CPASYNC16(b0 + sbyte + 16,           ah + 8);
        CPASYNC16(b0 + 2 * ARR + sbyte,      al);
        CPASYNC16(b0 + 2 * ARR + sbyte + 16, al + 8);
        CPASYNC16(b0 + 4 * ARR + sbyte,      bh);
        CPASYNC16(b0 + 4 * ARR + sbyte + 16, bh + 8);
        CPASYNC16(b0 + 6 * ARR + sbyte,      bl);
        CPASYNC16(b0 + 6 * ARR + sbyte + 16, bl + 8);
    };

    stage(0, 0);
    CPCOMMIT();
    CPWAIT0();
    __syncthreads();

    for (int s = 0; s < nslab; s++) {
        const int p = s & 1;
        if (s + 1 < nslab) {
            stage(s + 1, p ^ 1);
            CPCOMMIT();
        }
        const uint32_t pb = smem_u + p * BUFB;
#pragma unroll
        for (int kk = 0; kk < 2; kk++) {
            const uint32_t ko = kk * 32;
            uint32_t ah[2][4], al[2][4];
            LDSM4(ah[0][0], ah[0][1], ah[0][2], ah[0][3], pb + aOff[0] + ko);
            LDSM4(ah[1][0], ah[1][1], ah[1][2], ah[1][3], pb + aOff[1] + ko);
            LDSM4(al[0][0], al[0][1], al[0][2], al[0][3], pb + 2 * ARR + aOff[0] + ko);
            LDSM4(al[1][0], al[1][1], al[1][2], al[1][3], pb + 2 * ARR + aOff[1] + ko);
#pragma unroll
            for (int np = 0; np < 4; np++) {
                uint32_t bh[4], bl[4];
                LDSM4(bh[0], bh[1], bh[2], bh[3], pb + 4 * ARR + bOff[np] + ko);
                LDSM4(bl[0], bl[1], bl[2], bl[3], pb + 6 * ARR + bOff[np] + ko);
#pragma unroll
                for (int mt = 0; mt < 2; mt++) {
                    mma16816(acc[mt][2 * np + 0], ah[mt], bh[0], bh[1]);
                    mma16816(acc[mt][2 * np + 0], ah[mt], bl[0], bl[1]);
                    mma16816(acc[mt][2 * np + 0], al[mt], bh[0], bh[1]);
                    mma16816(acc[mt][2 * np + 1], ah[mt], bh[2], bh[3]);
                    mma16816(acc[mt][2 * np + 1], ah[mt], bl[2], bl[3]);
                    mma16816(acc[mt][2 * np + 1], al[mt], bh[2], bh[3]);
                }
            }
        }
        CPWAIT0();
        __syncthreads();
    }

    // ---- epilogue ----
#pragma unroll
    for (int mt = 0; mt < 2; mt++) {
        const int row = bm + warp_m * 32 + mt * 16 + g;
        float ga[4], gb[4];
        if (WSUM > 0) {
#pragma unroll
            for (int i = 0; i < WSUM; i++) {
                ga[i] = gsum[(u64)row * GOUT + goff + i];
                gb[i] = gsum[(u64)(row + 8) * GOUT + goff + i];
            }
        }
#pragma unroll
        for (int nt = 0; nt < 8; nt++) {
            const int col = bn + warp_n * 64 + nt * 8 + t * 2;
            const float b0 = bias[col], b1 = bias[col + 1];
            float2 v0, v1;
            v0.x = acc[mt][nt][0] + b0;
            v0.y = acc[mt][nt][1] + b1;
            v1.x = acc[mt][nt][2] + b0;
            v1.y = acc[mt][nt][3] + b1;
            if (RELU_C) {
                v0.x = fmaxf(v0.x, 0.f); v0.y = fmaxf(v0.y, 0.f);
                v1.x = fmaxf(v1.x, 0.f); v1.y = fmaxf(v1.y, 0.f);
            }
            if (MUL_C) {
                float2 m0 = *(const float2*)(Cmul + (u64)row * N + col);
                float2 m1 = *(const float2*)(Cmul + (u64)(row + 8) * N + col);
                v0.x *= m0.x; v0.y *= m0.y;
                v1.x *= m1.x; v1.y *= m1.y;
            }
            if (WRITE_F32) {
                *(float2*)(C + (u64)row * N + col)       = v0;
                *(float2*)(C + (u64)(row + 8) * N + col) = v1;
            }
            if (WSUM == 0) {
                if (WRITE_SPLIT) {
                    float2 w0 = v0, w1 = v1;
                    if (SPLIT_RELU) {
                        w0.x = fmaxf(w0.x, 0.f); w0.y = fmaxf(w0.y, 0.f);
                        w1.x = fmaxf(w1.x, 0.f); w1.y = fmaxf(w1.y, 0.f);
                    }
                    uint32_t h0, l0, h1, l1;
                    split2(w0.x, w0.y, h0, l0);
                    split2(w1.x, w1.y, h1, l1);
                    *(uint32_t*)(Chi + (u64)row * N + col)       = h0;
                    *(uint32_t*)(Clo + (u64)row * N + col)       = l0;
                    *(uint32_t*)(Chi + (u64)(row + 8) * N + col) = h1;
                    *(uint32_t*)(Clo + (u64)(row + 8) * N + col) = l1;
                }
            } else {
                float2 r0 = make_float2(0.f, 0.f), r1 = make_float2(0.f, 0.f);
                {
                    float2 q0 = *(const float2*)(P0 + (u64)row * N + col);
                    float2 q1 = *(const float2*)(P0 + (u64)(row + 8) * N + col);
                    r0.x += ga[0] * q0.x; r0.y += ga[0] * q0.y;
                    r1.x += gb[0] * q1.x; r1.y += gb[0] * q1.y;
                }
                if (WSUM >= 3) {
                    float2 q0 = *(const float2*)(P1 + (u64)row * N + col);
                    float2 q1 = *(const float2*)(P1 + (u64)(row + 8) * N + col);
                    r0.x += ga[1] * q0.x; r0.y += ga[1] * q0.y;
                    r1.x += gb[1] * q1.x; r1.y += gb[1] * q1.y;
                }
                if (WSUM >= 4) {
                    float2 q0 = *(const float2*)(P2 + (u64)row * N + col);
                    float2 q1 = *(const float2*)(P2 + (u64)(row + 8) * N + col);
                    r0.x += ga[2] * q0.x; r0.y += ga[2] * q0.y;
                    r1.x += gb[2] * q1.x; r1.y += gb[2] * q1.y;
                }
                r0.x += ga[WSUM - 1] * v0.x; r0.y += ga[WSUM - 1] * v0.y;
                r1.x += gb[WSUM - 1] * v1.x; r1.y += gb[WSUM - 1] * v1.y;
                if (WSUM == 4) {
                    *(float2*)(Cw + (u64)row * N + col)       = r0;
                    *(float2*)(Cw + (u64)(row + 8) * N + col) = r1;
                } else if (WRITE_SPLIT) {
                    uint32_t h0, l0, h1, l1;
                    split2(r0.x, r0.y, h0, l0);
                    split2(r1.x, r1.y, h1, l1);
                    *(uint32_t*)(Chi + (u64)row * N + col)       = h0;
                    *(uint32_t*)(Clo + (u64)row * N + col)       = l0;
                    *(uint32_t*)(Chi + (u64)(row + 8) * N + col) = h1;
                    *(uint32_t*)(Clo + (u64)(row + 8) * N + col) = l1;
                }
            }
        }
    }
}

// transpose + bf16-split: W [K,N] fp32 -> Wh/Wl [N,K] bf16
__global__ void tsplit_kernel(const float* __restrict__ W,
                              bf16* __restrict__ Wh, bf16* __restrict__ Wl,
                              int K, int N)
{
    __shared__ float tile[32][33];
    const int k0 = blockIdx.y * 32, n0 = blockIdx.x * 32;
    const int tx = threadIdx.x, ty = threadIdx.y;
#pragma unroll
    for (int i = 0; i < 32; i += 8)
        tile[ty + i][tx] = W[(u64)(k0 + ty + i) * N + n0 + tx];
    __syncthreads();
#pragma unroll
    for (int i = 0; i < 32; i += 8) {
        float v = tile[tx][ty + i];
        bf16 h = __float2bfloat16(v);
        bf16 l = __float2bfloat16(v - __bfloat162float(h));
        Wh[(u64)(n0 + ty + i) * K + k0 + tx] = h;
        Wl[(u64)(n0 + ty + i) * K + k0 + tx] = l;
    }
}

__global__ void asplit_kernel(const float* __restrict__ src,
                              bf16* __restrict__ hi, bf16* __restrict__ lo, int n)
{
    int idx = blockIdx.x * blockDim.x + threadIdx.x;
    if (idx >= n) return;
    float v = src[idx];
    bf16 h = __float2bfloat16(v);
    hi[idx] = h;
    lo[idx] = __float2bfloat16(v - __bfloat162float(h));
}

__global__ void ehidden_kernel(const float* __restrict__ em, const float* __restrict__ W0,
                               const float* __restrict__ b0,
                               bf16* __restrict__ hi, bf16* __restrict__ lo)
{
    int idx = blockIdx.x * blockDim.x + threadIdx.x;
    if (idx >= BATCH * EMH) return;
    int b = idx >> 8;
    int j = idx & (EMH - 1);
    float v = fmaxf(em[b] * W0[j] + b0[j], 0.f);
    bf16 h = __float2bfloat16(v);
    hi[idx] = h;
    lo[idx] = __float2bfloat16(v - __bfloat162float(h));
}

__global__ void logits_kernel(const float* __restrict__ gh, const float* __restrict__ W,
                              const float* __restrict__ b, float* __restrict__ logits)
{
    int warp = (blockIdx.x * blockDim.x + threadIdx.x) >> 5;
    int lane = threadIdx.x & 31;
    if (warp >= BATCH) return;
    const float* g = gh + warp * GH;
    float acc[GOUT];
#pragma unroll
    for (int j = 0; j < GOUT; j++) acc[j] = 0.f;
    for (int k = lane; k < GH; k += 32) {
        float gv = g[k];
        const float* wr = W + k * GOUT;
#pragma unroll
        for (int j = 0; j < GOUT; j++) acc[j] += gv * wr[j];
    }
#pragma unroll
    for (int j = 0; j < GOUT; j++) {
#pragma unroll
        for (int o = 16; o > 0; o >>= 1)
            acc[j] += __shfl_xor_sync(0xffffffffu, acc[j], o);
    }
    if (lane == 0) {
        float* dst = logits + warp * GOUT;
#pragma unroll
        for (int j = 0; j < GOUT; j++) dst[j] = acc[j] + b[j];
    }
}

__device__ __forceinline__ void route_m(const float* l, int m,
                                        float* g, float* oh, float* sm)
{
    float mx = l[0];
    for (int i = 1; i < m; i++) mx = fmaxf(mx, l[i]);
    float e[4], s = 0.f;
    for (int i = 0; i < m; i++) { e[i] = expf(l[i] - mx); s += e[i]; }
    float inv = 1.f / s;
    for (int i = 0; i < m; i++) sm[i] = e[i] * inv;
    int i1 = 0;
    for (int i = 1; i < m; i++) if (l[i] > l[i1]) i1 = i;
    int i2 = -1;
    for (int i = 0; i < m; i++) {
        if (i == i1) continue;
        if (i2 < 0 || l[i] > l[i2]) i2 = i;
    }
    float m2 = fmaxf(l[i1], l[i2]);
    float ea = expf(l[i1] - m2), eb = expf(l[i2] - m2);
    float si = 1.f / (ea + eb);
    g[i1] = ea * si; g[i2] = eb * si;
    oh[i1] = 1.f; oh[i2] = 1.f;
}

__global__ void routing_kernel(const float* __restrict__ logits, float* __restrict__ gdev,
                               float* __restrict__ og, float* __restrict__ ooh,
                               float* __restrict__ osm)
{
    int b = blockIdx.x * blockDim.x + threadIdx.x;
    if (b >= BATCH) return;
    float l[GOUT];
#pragma unroll
    for (int i = 0; i < GOUT; i++) l[i] = logits[b * GOUT + i];
    float g[GOUT], oh[GOUT], sm[GOUT];
#pragma unroll
    for (int i = 0; i < GOUT; i++) { g[i] = 0.f; oh[i] = 0.f; sm[i] = 0.f; }
    g[0] = 1.f; oh[0] = 1.f; sm[0] = 1.f;
    route_m(l + 1, 2, g + 1, oh + 1, sm + 1);
    route_m(l + 3, 3, g + 3, oh + 3, sm + 3);
    route_m(l + 6, 4, g + 6, oh + 6, sm + 6);
#pragma unroll
    for (int i = 0; i < GOUT; i++) {
        gdev[b * GOUT + i] = g[i];
        og  [b * GOUT + i] = g[i];
        ooh [b * GOUT + i] = oh[i];
        osm [b * GOUT + i] = sm[i];
    }
}

// inp2 = g[1]*o0 + g[2]*o1, split output (standalone; gates not ready in fc1 epi)
__global__ void wsum2_kernel(const float* __restrict__ gates,
                             const float* __restrict__ o0, const float* __restrict__ o1,
                             bf16* __restrict__ dsth, bf16* __restrict__ dstl)
{
    int idx = blockIdx.x * blockDim.x + threadIdx.x;
    if (idx >= BATCH * (HDIM / 4)) return;
    int b = idx / (HDIM / 4);
    const float* g = gates + b * GOUT + 1;
    float4 r = make_float4(0.f, 0.f, 0.f, 0.f);
    float w; float4 v;
    w = g[0]; v = ((const float4*)o0)[idx];
    r.x += w * v.x; r.y += w * v.y; r.z += w * v.z; r.w += w * v.w;
    w = g[1]; v = ((const float4*)o1)[idx];
    r.x += w * v.x; r.y += w * v.y; r.z += w * v.z; r.w += w * v.w;
    uint32_t h0, l0, h1, l1;
    split2(r.x, r.y, h0, l0);
    split2(r.z, r.w, h1, l1);
    ((uint2*)dsth)[idx] = make_uint2(h0, h1);
    ((uint2*)dstl)[idx] = make_uint2(l0, l1);
}

// final = last @ last_W + last_b   (N=18)
__global__ void final_kernel(const float* __restrict__ last, const float* __restrict__ W,
                             const float* __restrict__ b, float* __restrict__ out)
{
    int idx = blockIdx.x * blockDim.x + threadIdx.x;
    if (idx >= BATCH * OUTD) return;
    int row = idx / OUTD, o = idx % OUTD;
    const float4* lp = (const float4*)(last + row * HDIM);
    float s = 0.f;
    for (int k = 0; k < HDIM / 4; k++) {
        float4 v = lp[k];
        s += v.x * W[(4 * k + 0) * OUTD + o];
        s += v.y * W[(4 * k + 1) * OUTD + o];
        s += v.z * W[(4 * k + 2) * OUTD + o];
        s += v.w * W[(4 * k + 3) * OUTD + o];
    }
    out[idx] = s + b[o];
}

extern "C" void kernel_launch(void* const* d_in, const int* in_sizes, int n_in,
                              void* d_out, int out_size)
{
    const float* x        = (const float*)d_in[0];
    const float* em       = (const float*)d_in[1];
    const float* base_W0  = (const float*)d_in[2];
    const float* base_b0  = (const float*)d_in[3];
    const float* base_W1  = (const float*)d_in[4];
    const float* base_b1  = (const float*)d_in[5];
    const float* em_W0    = (const float*)d_in[6];
    const float* em_b0    = (const float*)d_in[7];
    const float* em_W1    = (const float*)d_in[8];
    const float* em_b1    = (const float*)d_in[9];
    const float* gate_W0  = (const float*)d_in[10];
    const float* gate_b0  = (const float*)d_in[11];
    const float* gate_W1  = (const float*)d_in[12];
    const float* gate_b1  = (const float*)d_in[13];
    const float* fc_W     = (const float*)d_in[14];
    const float* fc_b     = (const float*)d_in[15];
    const float* last_W   = (const float*)d_in[16];
    const float* last_b   = (const float*)d_in[17];
    float* out = (float*)d_out;

    float *base, *gh, *logits, *gates, *o0, *o1, *o2, *last;
    bf16 *xh, *xl, *h0h, *h0l, *bRh, *bRl, *ehh, *ehl, *gnh, *gnl;
    bf16 *o0h, *o0l, *iph, *ipl, *wbh, *wbl, *gwh, *gwl;
    cudaGetSymbolAddress((void**)&base, g_base);
    cudaGetSymbolAddress((void**)&gh,   g_gh);
    cudaGetSymbolAddress((void**)&logits, g_logits);
    cudaGetSymbolAddress((void**)&gates,  g_gates);
    cudaGetSymbolAddress((void**)&o0,  g_out0);
    cudaGetSymbolAddress((void**)&o1,  g_out1);
    cudaGetSymbolAddress((void**)&o2,  g_out2);
    cudaGetSymbolAddress((void**)&last, g_last);
    cudaGetSymbolAddress((void**)&xh,  g_xh);  cudaGetSymbolAddress((void**)&xl,  g_xl);
    cudaGetSymbolAddress((void**)&h0h, g_h0h); cudaGetSymbolAddress((void**)&h0l, g_h0l);
    cudaGetSymbolAddress((void**)&bRh, g_bRh); cudaGetSymbolAddress((void**)&bRl, g_bRl);
    cudaGetSymbolAddress((void**)&ehh, g_ehh); cudaGetSymbolAddress((void**)&ehl, g_ehl);
    cudaGetSymbolAddress((void**)&gnh, g_gnh); cudaGetSymbolAddress((void**)&gnl, g_gnl);
    cudaGetSymbolAddress((void**)&o0h, g_o0h); cudaGetSymbolAddress((void**)&o0l, g_o0l);
    cudaGetSymbolAddress((void**)&iph, g_iph); cudaGetSymbolAddress((void**)&ipl, g_ipl);
    cudaGetSymbolAddress((void**)&wbh, g_wbh); cudaGetSymbolAddress((void**)&wbl, g_wbl);
    cudaGetSymbolAddress((void**)&gwh, g_gwh); cudaGetSymbolAddress((void**)&gwl, g_gwl);

    // tc_gemm variants
    auto kA = tc_gemm_kernel<false, true,  false, true,  false, 0>;  // h0: split only
    auto kB = tc_gemm_kernel<false, false, true,  true,  true,  0>;  // base: f32 + split(relu)
    auto kC = tc_gemm_kernel<true,  true,  false, true,  false, 0>;  // gin: mul, split only
    auto kD = tc_gemm_kernel<false, true,  true,  false, false, 0>;  // gh / fc1: f32 only
    auto kE = tc_gemm_kernel<false, true,  true,  true,  false, 0>;  // fc0: f32 + split
    auto kF = tc_gemm_kernel<false, true,  true,  true,  false, 3>;  // fc2: f32 + wsum3 split
    auto kG = tc_gemm_kernel<false, true,  false, false, false, 4>;  // fc3: wsum4 f32 (last)
    cudaFuncSetAttribute(kA, cudaFuncAttributeMaxDynamicSharedMemorySize, SMEM_DYN);
    cudaFuncSetAttribute(kB, cudaFuncAttributeMaxDynamicSharedMemorySize, SMEM_DYN);
    cudaFuncSetAttribute(kC, cudaFuncAttributeMaxDynamicSharedMemorySize, SMEM_DYN);
    cudaFuncSetAttribute(kD, cudaFuncAttributeMaxDynamicSharedMemorySize, SMEM_DYN);
    cudaFuncSetAttribute(kE, cudaFuncAttributeMaxDynamicSharedMemorySize, SMEM_DYN);
    cudaFuncSetAttribute(kF, cudaFuncAttributeMaxDynamicSharedMemorySize, SMEM_DYN);
    cudaFuncSetAttribute(kG, cudaFuncAttributeMaxDynamicSharedMemorySize, SMEM_DYN);

    const int OFF_G  = BATCH * OUTD;
    const int OFF_OH = OFF_G + BATCH * GOUT;
    const int OFF_SM = OFF_OH + BATCH * GOUT;

    const dim3 blkT(32, 8);
    const dim3 gridTC(HDIM / 128, BATCH / 128);
    const dim3 gridTG(GH   / 128, BATCH / 128);

    // fork/join stream + events (created per call; only correctness+capture calls)
    cudaStream_t s2;
    cudaStreamCreateWithFlags(&s2, cudaStreamNonBlocking);
    cudaEvent_t eBase, eJoin;
    cudaEventCreateWithFlags(&eBase, cudaEventDisableTiming);
    cudaEventCreateWithFlags(&eJoin, cudaEventDisableTiming);

    // ---- prep (stream 0) ----
    tsplit_kernel<<<dim3(32, 2),  blkT>>>(base_W0, gwh + OFF_B0T, gwl + OFF_B0T, 64,   HDIM);
    tsplit_kernel<<<dim3(32, 32), blkT>>>(base_W1, gwh + OFF_B1T, gwl + OFF_B1T, HDIM, HDIM);
    tsplit_kernel<<<dim3(32, 8),  blkT>>>(em_W1,   gwh + OFF_EMT, gwl + OFF_EMT, EMH,  HDIM);
    tsplit_kernel<<<dim3(16, 32), blkT>>>(gate_W0, gwh + OFF_G0T, gwl + OFF_G0T, HDIM, GH);
    for (int m = 0; m < 4; m++)
        tsplit_kernel<<<dim3(32, 32), blkT>>>(fc_W + (u64)m * HDIM * HDIM,
                                              wbh + (u64)m * HDIM * HDIM,
                                              wbl + (u64)m * HDIM * HDIM, HDIM, HDIM);
    asplit_kernel<<<(BATCH * 64 + 255) / 256, 256>>>(x, xh, xl, BATCH * 64);
    ehidden_kernel<<<(BATCH * EMH + 255) / 256, 256>>>(em, em_W0, em_b0, ehh, ehl);

    // ---- shared prefix: h0, base (stream 0) ----
    kA<<<gridTC, 256, SMEM_DYN>>>(xh, xl, gwh + OFF_B0T, gwl + OFF_B0T, base_b0, nullptr,
                                  nullptr, h0h, h0l, nullptr, nullptr, 0, nullptr, nullptr, nullptr, HDIM, 64);
    kB<<<gridTC, 256, SMEM_DYN>>>(h0h, h0l, gwh + OFF_B1T, gwl + OFF_B1T, base_b1, nullptr,
                                  base, bRh, bRl, nullptr, nullptr, 0, nullptr, nullptr, nullptr, HDIM, HDIM);
    cudaEventRecord(eBase, 0);

    // ---- branch 2 (s2): fc0, fc1 (independent of routing) ----
    cudaStreamWaitEvent(s2, eBase, 0);
    kE<<<gridTC, 256, SMEM_DYN, s2>>>(bRh, bRl, wbh + 0ull * HDIM * HDIM, wbl + 0ull * HDIM * HDIM,
                                      fc_b + 0 * HDIM, nullptr, o0, o0h, o0l, nullptr, nullptr, 0,
                                      nullptr, nullptr, nullptr, HDIM, HDIM);
    kD<<<gridTC, 256, SMEM_DYN, s2>>>(o0h, o0l, wbh + 1ull * HDIM * HDIM, wbl + 1ull * HDIM * HDIM,
                                      fc_b + 1 * HDIM, nullptr, o1, nullptr, nullptr, nullptr, nullptr, 0,
                                      nullptr, nullptr, nullptr, HDIM, HDIM);
    cudaEventRecord(eJoin, s2);

    // ---- branch 1 (stream 0): gating ----
    kC<<<gridTC, 256, SMEM_DYN>>>(ehh, ehl, gwh + OFF_EMT, gwl + OFF_EMT, em_b1, base,
                                  nullptr, gnh, gnl, nullptr, nullptr, 0, nullptr, nullptr, nullptr, HDIM, EMH);
    kD<<<gridTG, 256, SMEM_DYN>>>(gnh, gnl, gwh + OFF_G0T, gwl + OFF_G0T, gate_b0, nullptr,
                                  gh, nullptr, nullptr, nullptr, nullptr, 0, nullptr, nullptr, nullptr, GH, HDIM);
    logits_kernel<<<(BATCH * 32 + 255) / 256, 256>>>(gh, gate_W1, gate_b1, logits);
    routing_kernel<<<(BATCH + 255) / 256, 256>>>(logits, gates, out + OFF_G, out + OFF_OH, out + OFF_SM);

    // ---- join, then tail (stream 0) ----
    cudaStreamWaitEvent((cudaStream_t)0, eJoin, 0);
    wsum2_kernel<<<(BATCH * HDIM / 4 + 255) / 256, 256>>>(gates, o0, o1, iph, ipl);
    kF<<<gridTC, 256, SMEM_DYN>>>(iph, ipl, wbh + 2ull * HDIM * HDIM, wbl + 2ull * HDIM * HDIM,
                                  fc_b + 2 * HDIM, nullptr, o2, iph, ipl, nullptr, gates, 3,
                                  o0, o1, nullptr, HDIM, HDIM);
    kG<<<gridTC, 256, SMEM_DYN>>>(iph, ipl, wbh + 3ull * HDIM * HDIM, wbl + 3ull * HDIM * HDIM,
                                  fc_b + 3 * HDIM, nullptr, nullptr, nullptr, nullptr, last, gates, 6,
                                  o0, o1, o2, HDIM, HDIM);
    final_kernel<<<(BATCH * OUTD + 255) / 256, 256>>>(last, last_W, last_b, out);
}